// round 1
// baseline (speedup 1.0000x reference)
#include <cuda_runtime.h>
#include <math.h>

// Problem constants
#define Bz 8
#define Sq 1024
#define Dm 1024
#define Hh 16
#define DH 64
#define Ii 4096
#define NQKV 3072           // H * 3 * DH
#define ROWS (Bz * Sq)      // 8192

// ---------------- scratch (static device memory; no allocations) ----------------
__device__ float g_Bqkv[Dm * NQKV];          // packed (D, H*3DH) row-major
__device__ float g_q[Bz * Hh * Sq * DH];     // (b,h,s,d), pre-scaled by sqrt(DH)
__device__ float g_k[Bz * Hh * Sq * DH];
__device__ float g_v[Bz * Hh * Sq * DH];
__device__ float g_ctx[ROWS * Dm];           // (b,s,h*DH) == (B,S,D)
__device__ float g_attn[ROWS * Dm];
__device__ float g_x[ROWS * Dm];
__device__ float g_h[ROWS * Ii];
__device__ float g_y[ROWS * Dm];

// ---------------- Wqkv repack: (H,D,3DH) -> (D, H*3DH) ----------------
__global__ void pack_wqkv_kernel(const float* __restrict__ w, float* __restrict__ out) {
    int idx = blockIdx.x * 256 + threadIdx.x;
    if (idx < Hh * Dm * 3 * DH) {
        int e = idx % (3 * DH);
        int d = (idx / (3 * DH)) % Dm;
        int h = idx / (3 * DH * Dm);
        out[d * NQKV + h * (3 * DH) + e] = w[idx];
    }
}

// ---------------- SGEMM: C(M,N) = A(M,K) @ B(K,N) + bias, epilogue variants ----------------
// EPI 0: C[r*N+c] = v + bias[c]
// EPI 1: qkv scatter: c -> (h = c/192, e = c%192); q gets *8 scale
// EPI 2: C[r*N+c] = gelu_erf(v + bias[c])
template <int EPI>
__global__ __launch_bounds__(256, 2)
void sgemm_kernel(const float* __restrict__ A, const float* __restrict__ B,
                  const float* __restrict__ bias, float* __restrict__ C,
                  float* __restrict__ qb, float* __restrict__ kb, float* __restrict__ vb,
                  int M, int N, int K) {
    constexpr int BM = 128, BN = 128, BK = 8, TM = 8, TN = 8;
    __shared__ float As[BK][BM];
    __shared__ float Bs[BK][BN];

    const int tid = threadIdx.x;
    const int bm = blockIdx.y, bn = blockIdx.x;

    const int arow = tid >> 1;            // 0..127
    const int acol = (tid & 1) * 4;       // 0 or 4
    const int brow = tid >> 5;            // 0..7
    const int bcol = (tid & 31) * 4;      // 0..124

    const float* Aptr = A + (size_t)(bm * BM + arow) * K + acol;
    const float* Bptr = B + (size_t)brow * N + bn * BN + bcol;

    const int trow = (tid >> 4) * TM;
    const int tcol = (tid & 15) * TN;

    float acc[TM][TN];
#pragma unroll
    for (int i = 0; i < TM; i++)
#pragma unroll
        for (int j = 0; j < TN; j++) acc[i][j] = 0.f;

    const int nt = K / BK;
    float4 aReg = *(const float4*)Aptr;
    float4 bReg = *(const float4*)Bptr;

    for (int t = 0; t < nt; ++t) {
        As[acol + 0][arow] = aReg.x;
        As[acol + 1][arow] = aReg.y;
        As[acol + 2][arow] = aReg.z;
        As[acol + 3][arow] = aReg.w;
        *(float4*)&Bs[brow][bcol] = bReg;
        __syncthreads();

        if (t + 1 < nt) {
            aReg = *(const float4*)(Aptr + (size_t)(t + 1) * BK);
            bReg = *(const float4*)(Bptr + (size_t)(t + 1) * BK * N);
        }

#pragma unroll
        for (int k = 0; k < BK; ++k) {
            float a[TM], b[TN];
            *(float4*)&a[0] = *(const float4*)&As[k][trow];
            *(float4*)&a[4] = *(const float4*)&As[k][trow + 4];
            *(float4*)&b[0] = *(const float4*)&Bs[k][tcol];
            *(float4*)&b[4] = *(const float4*)&Bs[k][tcol + 4];
#pragma unroll
            for (int i = 0; i < TM; i++)
#pragma unroll
                for (int j = 0; j < TN; j++)
                    acc[i][j] = fmaf(a[i], b[j], acc[i][j]);
        }
        __syncthreads();
    }

    // epilogue
#pragma unroll
    for (int i = 0; i < TM; i++) {
        const int r = bm * BM + trow + i;
#pragma unroll
        for (int j = 0; j < TN; j++) {
            const int c = bn * BN + tcol + j;
            float v = acc[i][j] + bias[c];
            if (EPI == 0) {
                C[(size_t)r * N + c] = v;
            } else if (EPI == 2) {
                C[(size_t)r * N + c] = 0.5f * v * (1.0f + erff(v * 0.70710678118654752f));
            } else {
                // qkv scatter
                const int h = c / (3 * DH);
                const int e = c - h * (3 * DH);
                const int b_ = r >> 10;
                const int s_ = r & 1023;
                const size_t base = ((size_t)(b_ * Hh + h) * Sq + s_) * DH;
                if (e < DH)            qb[base + e]            = v * 8.0f;   // sqrt(DH)=8
                else if (e < 2 * DH)   kb[base + e - DH]       = v;
                else                   vb[base + e - 2 * DH]   = v;
            }
        }
    }
}

// ---------------- fused flash attention ----------------
// grid: (S/64, H, B), 64 threads. Each thread owns one q row (online softmax).
__global__ __launch_bounds__(64)
void attn_kernel(const float* __restrict__ qg, const float* __restrict__ kg,
                 const float* __restrict__ vg, const unsigned char* __restrict__ maskg,
                 float* __restrict__ ctx) {
    __shared__ float Ks[64 * 64];
    __shared__ float Vs[64 * 64];
    __shared__ unsigned char Ms[64];

    const int tid = threadIdx.x;
    const int qt = blockIdx.x, h = blockIdx.y, b = blockIdx.z;
    const int srow = qt * 64 + tid;
    const size_t bh = (size_t)(b * Hh + h) * Sq;

    float qreg[DH];
    {
        const float4* q4 = (const float4*)(qg + (bh + srow) * DH);
#pragma unroll
        for (int i = 0; i < 16; i++) {
            float4 tq = q4[i];
            qreg[4 * i + 0] = tq.x; qreg[4 * i + 1] = tq.y;
            qreg[4 * i + 2] = tq.z; qreg[4 * i + 3] = tq.w;
        }
    }

    float accv[DH];
#pragma unroll
    for (int i = 0; i < DH; i++) accv[i] = 0.f;
    float m = -1e30f, l = 0.f;

    for (int kt = 0; kt < Sq / 64; kt++) {
        // cooperative K/V tile load (64x64 floats each)
        const float4* k4 = (const float4*)(kg + (bh + kt * 64) * DH);
        const float4* v4 = (const float4*)(vg + (bh + kt * 64) * DH);
        float4* Ks4 = (float4*)Ks;
        float4* Vs4 = (float4*)Vs;
#pragma unroll
        for (int it = 0; it < 16; it++) {
            int idx = tid + it * 64;          // 1024 float4s
            Ks4[idx] = k4[idx];
            Vs4[idx] = v4[idx];
        }
        Ms[tid] = maskg[b * Sq + kt * 64 + tid];
        __syncthreads();

#pragma unroll 4
        for (int j = 0; j < 64; j++) {
            if (!Ms[j]) {
                const float4* kr = (const float4*)&Ks[j * 64];
                float s0 = 0.f, s1 = 0.f, s2 = 0.f, s3 = 0.f;
#pragma unroll
                for (int i = 0; i < 16; i += 4) {
                    float4 t0 = kr[i], t1 = kr[i + 1], t2 = kr[i + 2], t3 = kr[i + 3];
                    s0 = fmaf(qreg[4*i+0], t0.x, s0); s0 = fmaf(qreg[4*i+1], t0.y, s0);
                    s0 = fmaf(qreg[4*i+2], t0.z, s0); s0 = fmaf(qreg[4*i+3], t0.w, s0);
                    s1 = fmaf(qreg[4*i+4], t1.x, s1); s1 = fmaf(qreg[4*i+5], t1.y, s1);
                    s1 = fmaf(qreg[4*i+6], t1.z, s1); s1 = fmaf(qreg[4*i+7], t1.w, s1);
                    s2 = fmaf(qreg[4*i+8], t2.x, s2); s2 = fmaf(qreg[4*i+9], t2.y, s2);
                    s2 = fmaf(qreg[4*i+10], t2.z, s2); s2 = fmaf(qreg[4*i+11], t2.w, s2);
                    s3 = fmaf(qreg[4*i+12], t3.x, s3); s3 = fmaf(qreg[4*i+13], t3.y, s3);
                    s3 = fmaf(qreg[4*i+14], t3.z, s3); s3 = fmaf(qreg[4*i+15], t3.w, s3);
                }
                float s = (s0 + s1) + (s2 + s3);

                if (s > m) {
                    float corr = __expf(m - s);
                    l *= corr;
#pragma unroll
                    for (int dd = 0; dd < DH; dd++) accv[dd] *= corr;
                    m = s;
                }
                float p = __expf(s - m);
                l += p;
                const float4* vr = (const float4*)&Vs[j * 64];
#pragma unroll
                for (int i = 0; i < 16; i++) {
                    float4 tv = vr[i];
                    accv[4*i+0] = fmaf(p, tv.x, accv[4*i+0]);
                    accv[4*i+1] = fmaf(p, tv.y, accv[4*i+1]);
                    accv[4*i+2] = fmaf(p, tv.z, accv[4*i+2]);
                    accv[4*i+3] = fmaf(p, tv.w, accv[4*i+3]);
                }
            }
        }
        __syncthreads();
    }

    // write ctx in (b, s, h, d) layout == (B,S,D)
    const float inv_l = 1.0f / l;
    float* orow = ctx + ((size_t)(b * Sq + srow) * Hh + h) * DH;
    float4* o4 = (float4*)orow;
#pragma unroll
    for (int i = 0; i < 16; i++) {
        float4 t;
        t.x = accv[4*i+0] * inv_l; t.y = accv[4*i+1] * inv_l;
        t.z = accv[4*i+2] * inv_l; t.w = accv[4*i+3] * inv_l;
        o4[i] = t;
    }
}

// ---------------- fused add + LayerNorm (rows of 1024) ----------------
__global__ __launch_bounds__(256)
void addln_kernel(const float* __restrict__ a, const float* __restrict__ b,
                  const float* __restrict__ g, const float* __restrict__ bt,
                  float* __restrict__ o) {
    __shared__ float redS[8], redQ[8], outMV[2];
    const int row = blockIdx.x;
    const int t = threadIdx.x;
    const float* ar = a + (size_t)row * Dm;
    const float* br = b + (size_t)row * Dm;

    float v[4];
    float s = 0.f, sq = 0.f;
#pragma unroll
    for (int i = 0; i < 4; i++) {
        int idx = t + i * 256;
        float x = ar[idx] + br[idx];
        v[i] = x;
        s += x;
        sq = fmaf(x, x, sq);
    }
#pragma unroll
    for (int off = 16; off; off >>= 1) {
        s += __shfl_xor_sync(0xFFFFFFFFu, s, off);
        sq += __shfl_xor_sync(0xFFFFFFFFu, sq, off);
    }
    if ((t & 31) == 0) { redS[t >> 5] = s; redQ[t >> 5] = sq; }
    __syncthreads();
    if (t < 32) {
        float s2 = (t < 8) ? redS[t] : 0.f;
        float q2 = (t < 8) ? redQ[t] : 0.f;
#pragma unroll
        for (int off = 4; off; off >>= 1) {
            s2 += __shfl_xor_sync(0xFFFFFFFFu, s2, off);
            q2 += __shfl_xor_sync(0xFFFFFFFFu, q2, off);
        }
        if (t == 0) {
            float mean = s2 * (1.0f / Dm);
            float var = q2 * (1.0f / Dm) - mean * mean;
            outMV[0] = mean;
            outMV[1] = rsqrtf(var + 1e-5f);
        }
    }
    __syncthreads();
    const float mean = outMV[0], rstd = outMV[1];
    float* orow = o + (size_t)row * Dm;
#pragma unroll
    for (int i = 0; i < 4; i++) {
        int idx = t + i * 256;
        orow[idx] = (v[i] - mean) * rstd * g[idx] + bt[idx];
    }
}

// ---------------- launch ----------------
extern "C" void kernel_launch(void* const* d_in, const int* in_sizes, int n_in,
                              void* d_out, int out_size) {
    const float* seq  = (const float*)d_in[0];
    const unsigned char* mask = (const unsigned char*)d_in[1];
    const float* Wqkv = (const float*)d_in[2];
    const float* bqkv = (const float*)d_in[3];   // (H,192) flat == packed col order
    const float* Wo   = (const float*)d_in[4];
    const float* bo   = (const float*)d_in[5];
    const float* g1   = (const float*)d_in[6];
    const float* b1   = (const float*)d_in[7];
    const float* Wi   = (const float*)d_in[8];
    const float* bi   = (const float*)d_in[9];
    const float* Wout = (const float*)d_in[10];
    const float* bout = (const float*)d_in[11];
    const float* g2   = (const float*)d_in[12];
    const float* b2   = (const float*)d_in[13];
    float* out = (float*)d_out;

    float *Bqkv, *q, *k, *v, *ctx, *attn, *x, *hb, *y;
    cudaGetSymbolAddress((void**)&Bqkv, g_Bqkv);
    cudaGetSymbolAddress((void**)&q,    g_q);
    cudaGetSymbolAddress((void**)&k,    g_k);
    cudaGetSymbolAddress((void**)&v,    g_v);
    cudaGetSymbolAddress((void**)&ctx,  g_ctx);
    cudaGetSymbolAddress((void**)&attn, g_attn);
    cudaGetSymbolAddress((void**)&x,    g_x);
    cudaGetSymbolAddress((void**)&hb,   g_h);
    cudaGetSymbolAddress((void**)&y,    g_y);

    // 1. pack Wqkv -> (D, 3072)
    pack_wqkv_kernel<<<(Hh * Dm * 3 * DH + 255) / 256, 256>>>(Wqkv, Bqkv);

    // 2. QKV projection + split/scale
    sgemm_kernel<1><<<dim3(NQKV / 128, ROWS / 128), 256>>>(
        seq, Bqkv, bqkv, nullptr, q, k, v, ROWS, NQKV, Dm);

    // 3. fused attention -> ctx (B,S,D)
    attn_kernel<<<dim3(Sq / 64, Hh, Bz), 64>>>(q, k, v, mask, ctx);

    // 4. output projection
    sgemm_kernel<0><<<dim3(Dm / 128, ROWS / 128), 256>>>(
        ctx, Wo, bo, attn, nullptr, nullptr, nullptr, ROWS, Dm, Dm);

    // 5. x = LN(seq + attn)
    addln_kernel<<<ROWS, 256>>>(seq, attn, g1, b1, x);

    // 6. h = gelu(x @ Wi + bi)
    sgemm_kernel<2><<<dim3(Ii / 128, ROWS / 128), 256>>>(
        x, Wi, bi, hb, nullptr, nullptr, nullptr, ROWS, Ii, Dm);

    // 7. y = h @ Wout + bout
    sgemm_kernel<0><<<dim3(Dm / 128, ROWS / 128), 256>>>(
        hb, Wout, bout, y, nullptr, nullptr, nullptr, ROWS, Dm, Ii);

    // 8. out = LN(x + y)
    addln_kernel<<<ROWS, 256>>>(x, y, g2, b2, out);
}

// round 3
// speedup vs baseline: 1.8537x; 1.8537x over previous
#include <cuda_runtime.h>
#include <cuda_bf16.h>
#include <math.h>
#include <stdint.h>

#define Bz 8
#define Sq 1024
#define Dm 1024
#define Hh 16
#define DH 64
#define Ii 4096
#define NQKV 3072
#define ROWS (Bz * Sq)

// ---------------- scratch (static device memory; no allocations) ----------------
__device__ __nv_bfloat16 g_seqh[ROWS * Dm], g_seql[ROWS * Dm];
__device__ __nv_bfloat16 g_Bqkvh[NQKV * Dm], g_Bqkvl[NQKV * Dm];
__device__ __nv_bfloat16 g_Woh[Dm * Dm], g_Wol[Dm * Dm];
__device__ __nv_bfloat16 g_Wih[Ii * Dm], g_Wil[Ii * Dm];
__device__ __nv_bfloat16 g_Wouth[Dm * Ii], g_Woutl[Dm * Ii];
__device__ float g_q[ROWS * Dm], g_k[ROWS * Dm], g_v[ROWS * Dm];
__device__ __nv_bfloat16 g_ctxh[ROWS * Dm], g_ctxl[ROWS * Dm];
__device__ float g_attn[ROWS * Dm];
__device__ float g_x[ROWS * Dm];
__device__ __nv_bfloat16 g_xh[ROWS * Dm], g_xl[ROWS * Dm];
__device__ __nv_bfloat16 g_hh[ROWS * Ii], g_hl[ROWS * Ii];
__device__ float g_y[ROWS * Dm];

// ---------------- helpers ----------------
__device__ __forceinline__ uint32_t smem_u32(const void* p) {
    uint32_t r;
    asm("{ .reg .u64 t; cvta.to.shared.u64 t, %1; cvt.u32.u64 %0, t; }" : "=r"(r) : "l"(p));
    return r;
}
#define CP_ASYNC16(dst, src) \
    asm volatile("cp.async.cg.shared.global [%0], [%1], 16;" :: "r"(dst), "l"(src) : "memory")
#define CP_COMMIT() asm volatile("cp.async.commit_group;" ::: "memory")
#define CP_WAIT1()  asm volatile("cp.async.wait_group 1;" ::: "memory")
#define CP_WAIT0()  asm volatile("cp.async.wait_group 0;" ::: "memory")

__device__ __forceinline__ void mma16816(float* d, const uint32_t* a, const uint32_t* b) {
    asm volatile(
        "mma.sync.aligned.m16n8k16.row.col.f32.bf16.bf16.f32 "
        "{%0,%1,%2,%3}, {%4,%5,%6,%7}, {%8,%9}, {%0,%1,%2,%3};"
        : "+f"(d[0]), "+f"(d[1]), "+f"(d[2]), "+f"(d[3])
        : "r"(a[0]), "r"(a[1]), "r"(a[2]), "r"(a[3]), "r"(b[0]), "r"(b[1]));
}

// ---------------- weight pack: transpose (K,N)->(N,K) + bf16 hi/lo split ----------------
__global__ void packW_kernel(const float* __restrict__ w, __nv_bfloat16* __restrict__ oh,
                             __nv_bfloat16* __restrict__ ol, int K, int N) {
    __shared__ float t[32][33];
    const int z = blockIdx.z;
    const float* in = w + (size_t)z * K * N;
    __nv_bfloat16* poh = oh + (size_t)z * N * K;
    __nv_bfloat16* pol = ol + (size_t)z * N * K;
    const int n0 = blockIdx.x * 32, k0 = blockIdx.y * 32;
    const int tx = threadIdx.x, ty = threadIdx.y;
#pragma unroll
    for (int i = 0; i < 32; i += 8)
        t[ty + i][tx] = in[(size_t)(k0 + ty + i) * N + n0 + tx];
    __syncthreads();
#pragma unroll
    for (int i = 0; i < 32; i += 8) {
        float v = t[tx][ty + i];
        __nv_bfloat16 hi = __float2bfloat16(v);
        float lo = v - __bfloat162float(hi);
        size_t o = (size_t)(n0 + ty + i) * K + k0 + tx;
        poh[o] = hi;
        pol[o] = __float2bfloat16(lo);
    }
}

// ---------------- fp32 -> bf16 hi/lo ----------------
__global__ void split_kernel(const float* __restrict__ in, __nv_bfloat16* __restrict__ oh,
                             __nv_bfloat16* __restrict__ ol, int n) {
    int i = (blockIdx.x * 256 + threadIdx.x) * 4;
    if (i < n) {
        float4 v = *(const float4*)(in + i);
        __nv_bfloat16 h0 = __float2bfloat16(v.x), h1 = __float2bfloat16(v.y);
        __nv_bfloat16 h2 = __float2bfloat16(v.z), h3 = __float2bfloat16(v.w);
        __nv_bfloat162* ph = (__nv_bfloat162*)(oh + i);
        ph[0] = __nv_bfloat162(h0, h1);
        ph[1] = __nv_bfloat162(h2, h3);
        __nv_bfloat162* pl = (__nv_bfloat162*)(ol + i);
        pl[0] = __nv_bfloat162(__float2bfloat16(v.x - __bfloat162float(h0)),
                               __float2bfloat16(v.y - __bfloat162float(h1)));
        pl[1] = __nv_bfloat162(__float2bfloat16(v.z - __bfloat162float(h2)),
                               __float2bfloat16(v.w - __bfloat162float(h3)));
    }
}

// ---------------- mma.sync split-bf16 GEMM ----------------
// C(M,N) = A(M,K) @ B(K,N); A (M,K) hi/lo bf16 row-major, B packed (N,K) hi/lo bf16.
// 128x128 block, BK=64, 8 warps each 64x32.
// Padded smem rows: 72 bf16 (144 B) -> conflict-free fragment loads & stores.
#define SROW 72
#define TILE_B (128 * SROW * 2)        // 18432 bytes per tile
#define STAGE_B (4 * TILE_B)           // Ah, Al, Bh, Bl
#define GEMM_SMEM (2 * STAGE_B)        // 147456 bytes

template <int EPI>
__global__ __launch_bounds__(256, 1)
void mma_gemm(const __nv_bfloat16* __restrict__ Ah, const __nv_bfloat16* __restrict__ Al,
              const __nv_bfloat16* __restrict__ Bh, const __nv_bfloat16* __restrict__ Bl,
              const float* __restrict__ bias, float* __restrict__ Cf,
              float* __restrict__ qb, float* __restrict__ kb, float* __restrict__ vb,
              __nv_bfloat16* __restrict__ Oh, __nv_bfloat16* __restrict__ Ol,
              int K, int N) {
    extern __shared__ char smem[];
    const uint32_t sb = smem_u32(smem);
    const int tid = threadIdx.x;
    const int w = tid >> 5, lane = tid & 31;
    const int g = lane >> 2, tig = lane & 3;
    const int bm = blockIdx.y, bn = blockIdx.x;
    const int wm = (w >> 2) * 64;       // warp row base within block tile
    const int wn = (w & 3) * 32;        // warp col base

    // gmem tile bases (bf16 elements)
    const __nv_bfloat16* gp[4] = {
        Ah + (size_t)bm * 128 * K, Al + (size_t)bm * 128 * K,
        Bh + (size_t)bn * 128 * K, Bl + (size_t)bn * 128 * K };

    // per-thread load slots: 4 chunks per tile; chunk c -> row c>>3, col-16B c&7
    int lrow[4], lcb[4];
#pragma unroll
    for (int i = 0; i < 4; i++) { int c = tid + i * 256; lrow[i] = c >> 3; lcb[i] = c & 7; }

    float acc[4][4][4];
#pragma unroll
    for (int mi = 0; mi < 4; mi++)
#pragma unroll
        for (int ni = 0; ni < 4; ni++)
#pragma unroll
            for (int e = 0; e < 4; e++) acc[mi][ni][e] = 0.f;

    const int NT = K / 64;

    auto issue_stage = [&](int kt) {
        const uint32_t dstS = sb + (kt & 1) * STAGE_B;
#pragma unroll
        for (int t = 0; t < 4; t++) {
            const __nv_bfloat16* src = gp[t] + kt * 64;
#pragma unroll
            for (int i = 0; i < 4; i++) {
                CP_ASYNC16(dstS + t * TILE_B + lrow[i] * (SROW * 2) + lcb[i] * 16,
                           src + (size_t)lrow[i] * K + lcb[i] * 8);
            }
        }
        CP_COMMIT();
    };

    issue_stage(0);

    for (int kt = 0; kt < NT; kt++) {
        if (kt + 1 < NT) { issue_stage(kt + 1); CP_WAIT1(); } else { CP_WAIT0(); }
        __syncthreads();

        const __nv_bfloat16* S = (const __nv_bfloat16*)(smem + (kt & 1) * STAGE_B);
        const __nv_bfloat16* Ash = S;
        const __nv_bfloat16* Asl = S + TILE_B / 2;
        const __nv_bfloat16* Bsh = S + TILE_B;          // TILE_B bytes = TILE_B/2 elems
        const __nv_bfloat16* Bsl = S + TILE_B / 2 * 3;

#pragma unroll
        for (int ks = 0; ks < 4; ks++) {
            const int k0 = ks * 16;
            uint32_t ah[4][4], al[4][4], bh[4][2], bl[4][2];
#pragma unroll
            for (int mi = 0; mi < 4; mi++) {
                const int r = wm + mi * 16 + g;
                const __nv_bfloat16* pa = Ash + r * SROW + k0 + tig * 2;
                const __nv_bfloat16* pl = Asl + r * SROW + k0 + tig * 2;
                ah[mi][0] = *(const uint32_t*)pa;
                ah[mi][1] = *(const uint32_t*)(pa + 8 * SROW);
                ah[mi][2] = *(const uint32_t*)(pa + 8);
                ah[mi][3] = *(const uint32_t*)(pa + 8 * SROW + 8);
                al[mi][0] = *(const uint32_t*)pl;
                al[mi][1] = *(const uint32_t*)(pl + 8 * SROW);
                al[mi][2] = *(const uint32_t*)(pl + 8);
                al[mi][3] = *(const uint32_t*)(pl + 8 * SROW + 8);
            }
#pragma unroll
            for (int ni = 0; ni < 4; ni++) {
                const int r = wn + ni * 8 + g;
                const __nv_bfloat16* pb = Bsh + r * SROW + k0 + tig * 2;
                const __nv_bfloat16* pc = Bsl + r * SROW + k0 + tig * 2;
                bh[ni][0] = *(const uint32_t*)pb;
                bh[ni][1] = *(const uint32_t*)(pb + 8);
                bl[ni][0] = *(const uint32_t*)pc;
                bl[ni][1] = *(const uint32_t*)(pc + 8);
            }
#pragma unroll
            for (int mi = 0; mi < 4; mi++)
#pragma unroll
                for (int ni = 0; ni < 4; ni++) {
                    mma16816(acc[mi][ni], ah[mi], bh[ni]);
                    mma16816(acc[mi][ni], ah[mi], bl[ni]);
                    mma16816(acc[mi][ni], al[mi], bh[ni]);
                }
        }
        __syncthreads();
    }

    // ---------------- epilogue ----------------
#pragma unroll
    for (int mi = 0; mi < 4; mi++) {
#pragma unroll
        for (int half = 0; half < 2; half++) {
            const int row = bm * 128 + wm + mi * 16 + g + half * 8;
#pragma unroll
            for (int ni = 0; ni < 4; ni++) {
                const int c = bn * 128 + wn + ni * 8 + tig * 2;
                float v0 = acc[mi][ni][half * 2 + 0] + bias[c];
                float v1 = acc[mi][ni][half * 2 + 1] + bias[c + 1];
                if (EPI == 0) {
                    *(float2*)&Cf[(size_t)row * N + c] = make_float2(v0, v1);
                } else if (EPI == 2) {
                    float g0 = 0.5f * v0 * (1.0f + erff(v0 * 0.70710678118654752f));
                    float g1 = 0.5f * v1 * (1.0f + erff(v1 * 0.70710678118654752f));
                    __nv_bfloat16 h0 = __float2bfloat16(g0), h1 = __float2bfloat16(g1);
                    *(__nv_bfloat162*)&Oh[(size_t)row * N + c] = __nv_bfloat162(h0, h1);
                    *(__nv_bfloat162*)&Ol[(size_t)row * N + c] =
                        __nv_bfloat162(__float2bfloat16(g0 - __bfloat162float(h0)),
                                       __float2bfloat16(g1 - __bfloat162float(h1)));
                } else {
                    const int h = c / 192;
                    const int e = c - h * 192;
                    const int b_ = row >> 10, s_ = row & 1023;
                    const size_t base = ((size_t)(b_ * Hh + h) * Sq + s_) * DH;
                    if (e < DH)
                        *(float2*)&qb[base + e] = make_float2(v0 * 8.0f, v1 * 8.0f);
                    else if (e < 2 * DH)
                        *(float2*)&kb[base + e - DH] = make_float2(v0, v1);
                    else
                        *(float2*)&vb[base + e - 2 * DH] = make_float2(v0, v1);
                }
            }
        }
    }
}

// ---------------- fused flash attention (fp32, scalar) ----------------
__global__ __launch_bounds__(64)
void attn_kernel(const float* __restrict__ qg, const float* __restrict__ kg,
                 const float* __restrict__ vg, const unsigned char* __restrict__ maskg,
                 __nv_bfloat16* __restrict__ ctxh, __nv_bfloat16* __restrict__ ctxl) {
    __shared__ float Ks[64 * 64];
    __shared__ float Vs[64 * 64];
    __shared__ unsigned char Ms[64];

    const int tid = threadIdx.x;
    const int qt = blockIdx.x, h = blockIdx.y, b = blockIdx.z;
    const int srow = qt * 64 + tid;
    const size_t bh = (size_t)(b * Hh + h) * Sq;

    float qreg[DH];
    {
        const float4* q4 = (const float4*)(qg + (bh + srow) * DH);
#pragma unroll
        for (int i = 0; i < 16; i++) {
            float4 tq = q4[i];
            qreg[4 * i + 0] = tq.x; qreg[4 * i + 1] = tq.y;
            qreg[4 * i + 2] = tq.z; qreg[4 * i + 3] = tq.w;
        }
    }

    float accv[DH];
#pragma unroll
    for (int i = 0; i < DH; i++) accv[i] = 0.f;
    float m = -1e30f, l = 0.f;

    for (int kt = 0; kt < Sq / 64; kt++) {
        const float4* k4 = (const float4*)(kg + (bh + kt * 64) * DH);
        const float4* v4 = (const float4*)(vg + (bh + kt * 64) * DH);
        float4* Ks4 = (float4*)Ks;
        float4* Vs4 = (float4*)Vs;
#pragma unroll
        for (int it = 0; it < 16; it++) {
            int idx = tid + it * 64;
            Ks4[idx] = k4[idx];
            Vs4[idx] = v4[idx];
        }
        Ms[tid] = maskg[b * Sq + kt * 64 + tid];
        __syncthreads();

#pragma unroll 4
        for (int j = 0; j < 64; j++) {
            if (!Ms[j]) {
                const float4* kr = (const float4*)&Ks[j * 64];
                float s0 = 0.f, s1 = 0.f, s2 = 0.f, s3 = 0.f;
#pragma unroll
                for (int i = 0; i < 16; i += 4) {
                    float4 t0 = kr[i], t1 = kr[i + 1], t2 = kr[i + 2], t3 = kr[i + 3];
                    s0 = fmaf(qreg[4*i+0], t0.x, s0); s0 = fmaf(qreg[4*i+1], t0.y, s0);
                    s0 = fmaf(qreg[4*i+2], t0.z, s0); s0 = fmaf(qreg[4*i+3], t0.w, s0);
                    s1 = fmaf(qreg[4*i+4], t1.x, s1); s1 = fmaf(qreg[4*i+5], t1.y, s1);
                    s1 = fmaf(qreg[4*i+6], t1.z, s1); s1 = fmaf(qreg[4*i+7], t1.w, s1);
                    s2 = fmaf(qreg[4*i+8], t2.x, s2); s2 = fmaf(qreg[4*i+9], t2.y, s2);
                    s2 = fmaf(qreg[4*i+10], t2.z, s2); s2 = fmaf(qreg[4*i+11], t2.w, s2);
                    s3 = fmaf(qreg[4*i+12], t3.x, s3); s3 = fmaf(qreg[4*i+13], t3.y, s3);
                    s3 = fmaf(qreg[4*i+14], t3.z, s3); s3 = fmaf(qreg[4*i+15], t3.w, s3);
                }
                float s = (s0 + s1) + (s2 + s3);

                if (s > m) {
                    float corr = __expf(m - s);
                    l *= corr;
#pragma unroll
                    for (int dd = 0; dd < DH; dd++) accv[dd] *= corr;
                    m = s;
                }
                float p = __expf(s - m);
                l += p;
                const float4* vr = (const float4*)&Vs[j * 64];
#pragma unroll
                for (int i = 0; i < 16; i++) {
                    float4 tv = vr[i];
                    accv[4*i+0] = fmaf(p, tv.x, accv[4*i+0]);
                    accv[4*i+1] = fmaf(p, tv.y, accv[4*i+1]);
                    accv[4*i+2] = fmaf(p, tv.z, accv[4*i+2]);
                    accv[4*i+3] = fmaf(p, tv.w, accv[4*i+3]);
                }
            }
        }
        __syncthreads();
    }

    const float inv_l = 1.0f / l;
    const size_t obase = ((size_t)(b * Sq + srow) * Hh + h) * DH;
    __nv_bfloat162* oh2 = (__nv_bfloat162*)(ctxh + obase);
    __nv_bfloat162* ol2 = (__nv_bfloat162*)(ctxl + obase);
#pragma unroll
    for (int i = 0; i < 32; i++) {
        float a0 = accv[2 * i] * inv_l, a1 = accv[2 * i + 1] * inv_l;
        __nv_bfloat16 h0 = __float2bfloat16(a0), h1 = __float2bfloat16(a1);
        oh2[i] = __nv_bfloat162(h0, h1);
        ol2[i] = __nv_bfloat162(__float2bfloat16(a0 - __bfloat162float(h0)),
                                __float2bfloat16(a1 - __bfloat162float(h1)));
    }
}

// ---------------- fused add + LayerNorm (+ optional bf16 hi/lo out) ----------------
__global__ __launch_bounds__(256)
void addln_kernel(const float* __restrict__ a, const float* __restrict__ b,
                  const float* __restrict__ g, const float* __restrict__ bt,
                  float* __restrict__ o, __nv_bfloat16* __restrict__ oh,
                  __nv_bfloat16* __restrict__ ol) {
    __shared__ float redS[8], redQ[8], outMV[2];
    const int row = blockIdx.x;
    const int t = threadIdx.x;
    const float* ar = a + (size_t)row * Dm;
    const float* br = b + (size_t)row * Dm;

    float v[4];
    float s = 0.f, sq = 0.f;
#pragma unroll
    for (int i = 0; i < 4; i++) {
        int idx = t + i * 256;
        float x = ar[idx] + br[idx];
        v[i] = x;
        s += x;
        sq = fmaf(x, x, sq);
    }
#pragma unroll
    for (int off = 16; off; off >>= 1) {
        s += __shfl_xor_sync(0xFFFFFFFFu, s, off);
        sq += __shfl_xor_sync(0xFFFFFFFFu, sq, off);
    }
    if ((t & 31) == 0) { redS[t >> 5] = s; redQ[t >> 5] = sq; }
    __syncthreads();
    if (t < 32) {
        float s2 = (t < 8) ? redS[t] : 0.f;
        float q2 = (t < 8) ? redQ[t] : 0.f;
#pragma unroll
        for (int off = 4; off; off >>= 1) {
            s2 += __shfl_xor_sync(0xFFFFFFFFu, s2, off);
            q2 += __shfl_xor_sync(0xFFFFFFFFu, q2, off);
        }
        if (t == 0) {
            float mean = s2 * (1.0f / Dm);
            float var = q2 * (1.0f / Dm) - mean * mean;
            outMV[0] = mean;
            outMV[1] = rsqrtf(var + 1e-5f);
        }
    }
    __syncthreads();
    const float mean = outMV[0], rstd = outMV[1];
    float* orow = o + (size_t)row * Dm;
#pragma unroll
    for (int i = 0; i < 4; i++) {
        int idx = t + i * 256;
        float y = (v[i] - mean) * rstd * g[idx] + bt[idx];
        orow[idx] = y;
        if (oh) {
            __nv_bfloat16 hi = __float2bfloat16(y);
            oh[(size_t)row * Dm + idx] = hi;
            ol[(size_t)row * Dm + idx] = __float2bfloat16(y - __bfloat162float(hi));
        }
    }
}

// ---------------- launch ----------------
extern "C" void kernel_launch(void* const* d_in, const int* in_sizes, int n_in,
                              void* d_out, int out_size) {
    const float* seq  = (const float*)d_in[0];
    const unsigned char* mask = (const unsigned char*)d_in[1];
    const float* Wqkv = (const float*)d_in[2];
    const float* bqkv = (const float*)d_in[3];
    const float* Wo   = (const float*)d_in[4];
    const float* bo   = (const float*)d_in[5];
    const float* g1   = (const float*)d_in[6];
    const float* b1   = (const float*)d_in[7];
    const float* Wi   = (const float*)d_in[8];
    const float* bi   = (const float*)d_in[9];
    const float* Wout = (const float*)d_in[10];
    const float* bout = (const float*)d_in[11];
    const float* g2   = (const float*)d_in[12];
    const float* b2   = (const float*)d_in[13];
    float* out = (float*)d_out;

    __nv_bfloat16 *seqh, *seql, *Bqkvh, *Bqkvl, *Woh, *Wol, *Wih, *Wil, *Wouth, *Woutl;
    __nv_bfloat16 *ctxh, *ctxl, *xh, *xl, *hh, *hl;
    float *q, *k, *v, *attn, *x, *y;
    cudaGetSymbolAddress((void**)&seqh, g_seqh);   cudaGetSymbolAddress((void**)&seql, g_seql);
    cudaGetSymbolAddress((void**)&Bqkvh, g_Bqkvh); cudaGetSymbolAddress((void**)&Bqkvl, g_Bqkvl);
    cudaGetSymbolAddress((void**)&Woh, g_Woh);     cudaGetSymbolAddress((void**)&Wol, g_Wol);
    cudaGetSymbolAddress((void**)&Wih, g_Wih);     cudaGetSymbolAddress((void**)&Wil, g_Wil);
    cudaGetSymbolAddress((void**)&Wouth, g_Wouth); cudaGetSymbolAddress((void**)&Woutl, g_Woutl);
    cudaGetSymbolAddress((void**)&ctxh, g_ctxh);   cudaGetSymbolAddress((void**)&ctxl, g_ctxl);
    cudaGetSymbolAddress((void**)&xh, g_xh);       cudaGetSymbolAddress((void**)&xl, g_xl);
    cudaGetSymbolAddress((void**)&hh, g_hh);       cudaGetSymbolAddress((void**)&hl, g_hl);
    cudaGetSymbolAddress((void**)&q, g_q);         cudaGetSymbolAddress((void**)&k, g_k);
    cudaGetSymbolAddress((void**)&v, g_v);         cudaGetSymbolAddress((void**)&attn, g_attn);
    cudaGetSymbolAddress((void**)&x, g_x);         cudaGetSymbolAddress((void**)&y, g_y);

    cudaFuncSetAttribute(mma_gemm<0>, cudaFuncAttributeMaxDynamicSharedMemorySize, GEMM_SMEM);
    cudaFuncSetAttribute(mma_gemm<1>, cudaFuncAttributeMaxDynamicSharedMemorySize, GEMM_SMEM);
    cudaFuncSetAttribute(mma_gemm<2>, cudaFuncAttributeMaxDynamicSharedMemorySize, GEMM_SMEM);

    // weight packing (transpose + hi/lo split)
    packW_kernel<<<dim3(192 / 32, Dm / 32, Hh), dim3(32, 8)>>>(Wqkv, Bqkvh, Bqkvl, Dm, 192);
    packW_kernel<<<dim3(Dm / 32, Dm / 32, 1), dim3(32, 8)>>>(Wo, Woh, Wol, Dm, Dm);
    packW_kernel<<<dim3(Ii / 32, Dm / 32, 1), dim3(32, 8)>>>(Wi, Wih, Wil, Dm, Ii);
    packW_kernel<<<dim3(Dm / 32, Ii / 32, 1), dim3(32, 8)>>>(Wout, Wouth, Woutl, Ii, Dm);

    // seq -> hi/lo
    split_kernel<<<(ROWS * Dm / 4 + 255) / 256, 256>>>(seq, seqh, seql, ROWS * Dm);

    // QKV projection + scatter/scale
    mma_gemm<1><<<dim3(NQKV / 128, ROWS / 128), 256, GEMM_SMEM>>>(
        seqh, seql, Bqkvh, Bqkvl, bqkv, nullptr, q, k, v, nullptr, nullptr, Dm, NQKV);

    // attention -> ctx hi/lo
    attn_kernel<<<dim3(Sq / 64, Hh, Bz), 64>>>(q, k, v, mask, ctxh, ctxl);

    // output projection
    mma_gemm<0><<<dim3(Dm / 128, ROWS / 128), 256, GEMM_SMEM>>>(
        ctxh, ctxl, Woh, Wol, bo, attn, nullptr, nullptr, nullptr, nullptr, nullptr, Dm, Dm);

    // x = LN(seq + attn)  (+ hi/lo for next GEMM)
    addln_kernel<<<ROWS, 256>>>(seq, attn, g1, b1, x, xh, xl);

    // h = gelu(x @ Wi + bi) -> hi/lo
    mma_gemm<2><<<dim3(Ii / 128, ROWS / 128), 256, GEMM_SMEM>>>(
        xh, xl, Wih, Wil, bi, nullptr, nullptr, nullptr, nullptr, hh, hl, Dm, Ii);

    // y = h @ Wout + bout
    mma_gemm<0><<<dim3(Dm / 128, ROWS / 128), 256, GEMM_SMEM>>>(
        hh, hl, Wouth, Woutl, bout, y, nullptr, nullptr, nullptr, nullptr, nullptr, Ii, Dm);

    // out = LN(x + y)
    addln_kernel<<<ROWS, 256>>>(x, y, g2, b2, out, nullptr, nullptr);
}

// round 6
// speedup vs baseline: 3.3160x; 1.7889x over previous
#include <cuda_runtime.h>
#include <cuda_fp16.h>
#include <math.h>
#include <stdint.h>

#define Bz 8
#define Sq 1024
#define Dm 1024
#define Hh 16
#define DH 64
#define Ii 4096
#define NQKV 3072
#define ROWS (Bz * Sq)

// ---------------- scratch (static device memory; no allocations) ----------------
__device__ __half g_seqh[ROWS * Dm], g_seql[ROWS * Dm];
__device__ __half g_Bqkvh[NQKV * Dm], g_Bqkvl[NQKV * Dm];
__device__ __half g_Woh[Dm * Dm], g_Wol[Dm * Dm];
__device__ __half g_Wih[Ii * Dm], g_Wil[Ii * Dm];
__device__ __half g_Wouth[Dm * Ii], g_Woutl[Dm * Ii];
__device__ __half g_qh[ROWS * Dm], g_ql[ROWS * Dm];
__device__ __half g_kh[ROWS * Dm], g_kl[ROWS * Dm];
__device__ __half g_vh[ROWS * Dm];
__device__ __half g_ctxh[ROWS * Dm];
__device__ float g_attn[ROWS * Dm];
__device__ float g_x[ROWS * Dm];
__device__ __half g_xh[ROWS * Dm];
__device__ __half g_hh[ROWS * Ii];
__device__ float g_y[ROWS * Dm];

// ---------------- helpers ----------------
__device__ __forceinline__ uint32_t smem_u32(const void* p) {
    uint32_t r;
    asm("{ .reg .u64 t; cvta.to.shared.u64 t, %1; cvt.u32.u64 %0, t; }" : "=r"(r) : "l"(p));
    return r;
}
#define CP_ASYNC16(dst, src) \
    asm volatile("cp.async.cg.shared.global [%0], [%1], 16;" :: "r"(dst), "l"(src) : "memory")
#define CP_COMMIT() asm volatile("cp.async.commit_group;" ::: "memory")
#define CP_WAIT1()  asm volatile("cp.async.wait_group 1;" ::: "memory")
#define CP_WAIT0()  asm volatile("cp.async.wait_group 0;" ::: "memory")

__device__ __forceinline__ void mma16816(float* d, const uint32_t* a, const uint32_t* b) {
    asm volatile(
        "mma.sync.aligned.m16n8k16.row.col.f32.f16.f16.f32 "
        "{%0,%1,%2,%3}, {%4,%5,%6,%7}, {%8,%9}, {%0,%1,%2,%3};"
        : "+f"(d[0]), "+f"(d[1]), "+f"(d[2]), "+f"(d[3])
        : "r"(a[0]), "r"(a[1]), "r"(a[2]), "r"(a[3]), "r"(b[0]), "r"(b[1]));
}
__device__ __forceinline__ uint32_t packh2(float a, float b) {
    __half2 h = __floats2half2_rn(a, b);
    return *(uint32_t*)&h;
}

// ---------------- weight pack: transpose (K,N)->(N,K) + fp16 hi/lo split ----------------
__global__ void packW_kernel(const float* __restrict__ w, __half* __restrict__ oh,
                             __half* __restrict__ ol, int K, int N) {
    __shared__ float t[32][33];
    const int z = blockIdx.z;
    const float* in = w + (size_t)z * K * N;
    __half* poh = oh + (size_t)z * N * K;
    __half* pol = ol + (size_t)z * N * K;
    const int n0 = blockIdx.x * 32, k0 = blockIdx.y * 32;
    const int tx = threadIdx.x, ty = threadIdx.y;
#pragma unroll
    for (int i = 0; i < 32; i += 8)
        t[ty + i][tx] = in[(size_t)(k0 + ty + i) * N + n0 + tx];
    __syncthreads();
#pragma unroll
    for (int i = 0; i < 32; i += 8) {
        float v = t[tx][ty + i];
        __half hi = __float2half_rn(v);
        size_t o = (size_t)(n0 + ty + i) * K + k0 + tx;
        poh[o] = hi;
        pol[o] = __float2half_rn(v - __half2float(hi));
    }
}

// ---------------- fp32 -> fp16 hi/lo ----------------
__global__ void split_kernel(const float* __restrict__ in, __half* __restrict__ oh,
                             __half* __restrict__ ol, int n) {
    int i = (blockIdx.x * 256 + threadIdx.x) * 4;
    if (i < n) {
        float4 v = *(const float4*)(in + i);
        __half h0 = __float2half_rn(v.x), h1 = __float2half_rn(v.y);
        __half h2 = __float2half_rn(v.z), h3 = __float2half_rn(v.w);
        __half2* ph = (__half2*)(oh + i);
        ph[0] = __halves2half2(h0, h1);
        ph[1] = __halves2half2(h2, h3);
        __half2* pl = (__half2*)(ol + i);
        pl[0] = __halves2half2(__float2half_rn(v.x - __half2float(h0)),
                               __float2half_rn(v.y - __half2float(h1)));
        pl[1] = __halves2half2(__float2half_rn(v.z - __half2float(h2)),
                               __float2half_rn(v.w - __half2float(h3)));
    }
}

// ---------------- mma.sync split-fp16 GEMM ----------------
// TERMS=3: acc = Ah*Bh + Ah*Bl + Al*Bh  (A hi/lo, B hi/lo)
// TERMS=2: acc = A*Bh + A*Bl            (A single fp16, B hi/lo)
#define SROW 72
#define TILE_H (128 * SROW)            // halves per tile
#define TILE_B (TILE_H * 2)            // 18432 bytes

template <int EPI, int TERMS>
__global__ __launch_bounds__(256, 1)
void mma_gemm(const __half* __restrict__ Ah, const __half* __restrict__ Al,
              const __half* __restrict__ Bh, const __half* __restrict__ Bl,
              const float* __restrict__ bias, float* __restrict__ Cf,
              __half* __restrict__ qh, __half* __restrict__ ql,
              __half* __restrict__ kh, __half* __restrict__ kl,
              __half* __restrict__ vh, __half* __restrict__ Oh,
              int K, int N) {
    constexpr int NTILES = (TERMS == 3) ? 4 : 3;
    constexpr int STAGE_B = NTILES * TILE_B;
    extern __shared__ char smem[];
    const uint32_t sb = smem_u32(smem);
    const int tid = threadIdx.x;
    const int w = tid >> 5, lane = tid & 31;
    const int g = lane >> 2, tig = lane & 3;
    const int bm = blockIdx.y, bn = blockIdx.x;
    const int wm = (w >> 2) * 64;
    const int wn = (w & 3) * 32;

    const __half* gp[4];
    gp[0] = Ah + (size_t)bm * 128 * K;
    if (TERMS == 3) {
        gp[1] = Al + (size_t)bm * 128 * K;
        gp[2] = Bh + (size_t)bn * 128 * K;
        gp[3] = Bl + (size_t)bn * 128 * K;
    } else {
        gp[1] = Bh + (size_t)bn * 128 * K;
        gp[2] = Bl + (size_t)bn * 128 * K;
        gp[3] = nullptr;
    }

    int lrow[4], lcb[4];
#pragma unroll
    for (int i = 0; i < 4; i++) { int c = tid + i * 256; lrow[i] = c >> 3; lcb[i] = c & 7; }

    float acc[4][4][4];
#pragma unroll
    for (int mi = 0; mi < 4; mi++)
#pragma unroll
        for (int ni = 0; ni < 4; ni++)
#pragma unroll
            for (int e = 0; e < 4; e++) acc[mi][ni][e] = 0.f;

    const int NT = K / 64;

    auto issue_stage = [&](int kt) {
        const uint32_t dstS = sb + (kt & 1) * STAGE_B;
#pragma unroll
        for (int t = 0; t < NTILES; t++) {
            const __half* src = gp[t] + kt * 64;
#pragma unroll
            for (int i = 0; i < 4; i++) {
                CP_ASYNC16(dstS + t * TILE_B + lrow[i] * (SROW * 2) + lcb[i] * 16,
                           src + (size_t)lrow[i] * K + lcb[i] * 8);
            }
        }
        CP_COMMIT();
    };

    issue_stage(0);

    for (int kt = 0; kt < NT; kt++) {
        if (kt + 1 < NT) { issue_stage(kt + 1); CP_WAIT1(); } else { CP_WAIT0(); }
        __syncthreads();

        const __half* S = (const __half*)(smem + (kt & 1) * STAGE_B);
        const __half* Ash = S;
        const __half* Asl = (TERMS == 3) ? S + TILE_H : nullptr;
        const __half* Bsh = (TERMS == 3) ? S + 2 * TILE_H : S + TILE_H;
        const __half* Bsl = (TERMS == 3) ? S + 3 * TILE_H : S + 2 * TILE_H;

#pragma unroll
        for (int ks = 0; ks < 4; ks++) {
            const int k0 = ks * 16;
            uint32_t ah[4][4], al[4][4], bh[4][2], bl[4][2];
#pragma unroll
            for (int mi = 0; mi < 4; mi++) {
                const int r = wm + mi * 16 + g;
                const __half* pa = Ash + r * SROW + k0 + tig * 2;
                ah[mi][0] = *(const uint32_t*)pa;
                ah[mi][1] = *(const uint32_t*)(pa + 8 * SROW);
                ah[mi][2] = *(const uint32_t*)(pa + 8);
                ah[mi][3] = *(const uint32_t*)(pa + 8 * SROW + 8);
                if (TERMS == 3) {
                    const __half* pl = Asl + r * SROW + k0 + tig * 2;
                    al[mi][0] = *(const uint32_t*)pl;
                    al[mi][1] = *(const uint32_t*)(pl + 8 * SROW);
                    al[mi][2] = *(const uint32_t*)(pl + 8);
                    al[mi][3] = *(const uint32_t*)(pl + 8 * SROW + 8);
                }
            }
#pragma unroll
            for (int ni = 0; ni < 4; ni++) {
                const int r = wn + ni * 8 + g;
                const __half* pb = Bsh + r * SROW + k0 + tig * 2;
                const __half* pc = Bsl + r * SROW + k0 + tig * 2;
                bh[ni][0] = *(const uint32_t*)pb;
                bh[ni][1] = *(const uint32_t*)(pb + 8);
                bl[ni][0] = *(const uint32_t*)pc;
                bl[ni][1] = *(const uint32_t*)(pc + 8);
            }
#pragma unroll
            for (int mi = 0; mi < 4; mi++)
#pragma unroll
                for (int ni = 0; ni < 4; ni++) {
                    mma16816(acc[mi][ni], ah[mi], bh[ni]);
                    mma16816(acc[mi][ni], ah[mi], bl[ni]);
                    if (TERMS == 3) mma16816(acc[mi][ni], al[mi], bh[ni]);
                }
        }
        __syncthreads();
    }

    // ---------------- epilogue ----------------
#pragma unroll
    for (int mi = 0; mi < 4; mi++) {
#pragma unroll
        for (int half_ = 0; half_ < 2; half_++) {
            const int row = bm * 128 + wm + mi * 16 + g + half_ * 8;
#pragma unroll
            for (int ni = 0; ni < 4; ni++) {
                const int c = bn * 128 + wn + ni * 8 + tig * 2;
                float v0 = acc[mi][ni][half_ * 2 + 0] + bias[c];
                float v1 = acc[mi][ni][half_ * 2 + 1] + bias[c + 1];
                if (EPI == 0) {
                    *(float2*)&Cf[(size_t)row * N + c] = make_float2(v0, v1);
                } else if (EPI == 2) {
                    float g0 = 0.5f * v0 * (1.0f + erff(v0 * 0.70710678118654752f));
                    float g1 = 0.5f * v1 * (1.0f + erff(v1 * 0.70710678118654752f));
                    *(__half2*)&Oh[(size_t)row * N + c] = __floats2half2_rn(g0, g1);
                } else {
                    const int h = c / 192;
                    const int e = c - h * 192;
                    const int b_ = row >> 10, s_ = row & 1023;
                    const size_t base = ((size_t)(b_ * Hh + h) * Sq + s_) * DH;
                    if (e < DH) {
                        float s0 = v0 * 8.0f, s1 = v1 * 8.0f;   // sqrt(DH)=8
                        __half h0 = __float2half_rn(s0), h1 = __float2half_rn(s1);
                        *(__half2*)&qh[base + e] = __halves2half2(h0, h1);
                        *(__half2*)&ql[base + e] =
                            __halves2half2(__float2half_rn(s0 - __half2float(h0)),
                                           __float2half_rn(s1 - __half2float(h1)));
                    } else if (e < 2 * DH) {
                        __half h0 = __float2half_rn(v0), h1 = __float2half_rn(v1);
                        *(__half2*)&kh[base + e - DH] = __halves2half2(h0, h1);
                        *(__half2*)&kl[base + e - DH] =
                            __halves2half2(__float2half_rn(v0 - __half2float(h0)),
                                           __float2half_rn(v1 - __half2float(h1)));
                    } else {
                        *(__half2*)&vh[base + e - 2 * DH] = __floats2half2_rn(v0, v1);
                    }
                }
            }
        }
    }
}

// ---------------- tensor-core flash attention ----------------
// grid (8, 16, 8) = (qblk, h, b); 256 threads, warp w owns rows w*16..+15.
// QK^T: 3-term fp16 hi/lo (fp32-accurate scores); softmax fp32 in registers;
// P*V: single-term fp16.
#define ASROW 72
__global__ __launch_bounds__(256, 2)
void attn_mma(const __half* __restrict__ qg, const __half* __restrict__ qlg,
              const __half* __restrict__ kg, const __half* __restrict__ klg,
              const __half* __restrict__ vg, const unsigned char* __restrict__ maskg,
              __half* __restrict__ ctx) {
    __shared__ __half Ksh[64 * ASROW];
    __shared__ __half Ksl[64 * ASROW];
    __shared__ __half Vth[64 * ASROW];
    __shared__ unsigned char Ms[64];

    const int tid = threadIdx.x;
    const int w = tid >> 5, lane = tid & 31;
    const int g = lane >> 2, tig = lane & 3;
    const int qblk = blockIdx.x, h = blockIdx.y, b = blockIdx.z;
    const size_t bh = (size_t)(b * Hh + h) * Sq;
    const int qrow0 = qblk * 128 + w * 16;

    // Q fragments (hi/lo) held in registers for the whole kernel
    uint32_t qfh[4][4], qfl[4][4];
#pragma unroll
    for (int ks = 0; ks < 4; ks++) {
        const int k0 = ks * 16 + tig * 2;
        const size_t r0 = (bh + qrow0 + g) * DH;
        const size_t r1 = (bh + qrow0 + g + 8) * DH;
        qfh[ks][0] = *(const uint32_t*)(qg + r0 + k0);
        qfh[ks][1] = *(const uint32_t*)(qg + r1 + k0);
        qfh[ks][2] = *(const uint32_t*)(qg + r0 + k0 + 8);
        qfh[ks][3] = *(const uint32_t*)(qg + r1 + k0 + 8);
        qfl[ks][0] = *(const uint32_t*)(qlg + r0 + k0);
        qfl[ks][1] = *(const uint32_t*)(qlg + r1 + k0);
        qfl[ks][2] = *(const uint32_t*)(qlg + r0 + k0 + 8);
        qfl[ks][3] = *(const uint32_t*)(qlg + r1 + k0 + 8);
    }

    float out[8][4];
#pragma unroll
    for (int nt = 0; nt < 8; nt++)
#pragma unroll
        for (int e = 0; e < 4; e++) out[nt][e] = 0.f;
    float m0 = -1e30f, m1 = -1e30f, l0 = 0.f, l1 = 0.f;

    for (int kt = 0; kt < 16; kt++) {
        // cooperative chunk load: K hi/lo row-major, V transposed (hi only)
#pragma unroll
        for (int i = 0; i < 8; i++) {
            int c = tid + i * 256;           // 2048 u32 slots
            int row = c >> 5, c2 = c & 31;
            const size_t gsrc = (bh + kt * 64 + row) * DH + c2 * 2;
            *(uint32_t*)&Ksh[row * ASROW + c2 * 2] = *(const uint32_t*)(kg + gsrc);
            *(uint32_t*)&Ksl[row * ASROW + c2 * 2] = *(const uint32_t*)(klg + gsrc);
            __half2 v2 = *(const __half2*)(vg + gsrc);
            Vth[(c2 * 2) * ASROW + row] = __low2half(v2);
            Vth[(c2 * 2 + 1) * ASROW + row] = __high2half(v2);
        }
        if (tid < 64) Ms[tid] = maskg[b * Sq + kt * 64 + tid];
        __syncthreads();

        // ---- S = Q K^T (3-term) ----
        float s[8][4];
#pragma unroll
        for (int nt = 0; nt < 8; nt++)
#pragma unroll
            for (int e = 0; e < 4; e++) s[nt][e] = 0.f;
#pragma unroll
        for (int ks = 0; ks < 4; ks++) {
            const int k0 = ks * 16 + tig * 2;
#pragma unroll
            for (int nt = 0; nt < 8; nt++) {
                const __half* pb = Ksh + (nt * 8 + g) * ASROW + k0;
                const __half* pc = Ksl + (nt * 8 + g) * ASROW + k0;
                uint32_t bhf[2] = { *(const uint32_t*)pb, *(const uint32_t*)(pb + 8) };
                uint32_t blf[2] = { *(const uint32_t*)pc, *(const uint32_t*)(pc + 8) };
                mma16816(s[nt], qfh[ks], bhf);
                mma16816(s[nt], qfl[ks], bhf);
                mma16816(s[nt], qfh[ks], blf);
            }
        }

        // ---- mask + online softmax ----
        float mx0 = -1e30f, mx1 = -1e30f;
#pragma unroll
        for (int nt = 0; nt < 8; nt++) {
            const int col = nt * 8 + tig * 2;
            if (Ms[col])     { s[nt][0] = -1e30f; s[nt][2] = -1e30f; }
            if (Ms[col + 1]) { s[nt][1] = -1e30f; s[nt][3] = -1e30f; }
            mx0 = fmaxf(mx0, fmaxf(s[nt][0], s[nt][1]));
            mx1 = fmaxf(mx1, fmaxf(s[nt][2], s[nt][3]));
        }
        mx0 = fmaxf(mx0, __shfl_xor_sync(0xffffffffu, mx0, 1));
        mx0 = fmaxf(mx0, __shfl_xor_sync(0xffffffffu, mx0, 2));
        mx1 = fmaxf(mx1, __shfl_xor_sync(0xffffffffu, mx1, 1));
        mx1 = fmaxf(mx1, __shfl_xor_sync(0xffffffffu, mx1, 2));
        const float mn0 = fmaxf(m0, mx0), mn1 = fmaxf(m1, mx1);
        const float sc0 = __expf(m0 - mn0), sc1 = __expf(m1 - mn1);
        m0 = mn0; m1 = mn1;
        float rs0 = 0.f, rs1 = 0.f;
#pragma unroll
        for (int nt = 0; nt < 8; nt++) {
            s[nt][0] = __expf(s[nt][0] - mn0);
            s[nt][1] = __expf(s[nt][1] - mn0);
            s[nt][2] = __expf(s[nt][2] - mn1);
            s[nt][3] = __expf(s[nt][3] - mn1);
            rs0 += s[nt][0] + s[nt][1];
            rs1 += s[nt][2] + s[nt][3];
            out[nt][0] *= sc0; out[nt][1] *= sc0;
            out[nt][2] *= sc1; out[nt][3] *= sc1;
        }
        rs0 += __shfl_xor_sync(0xffffffffu, rs0, 1);
        rs0 += __shfl_xor_sync(0xffffffffu, rs0, 2);
        rs1 += __shfl_xor_sync(0xffffffffu, rs1, 1);
        rs1 += __shfl_xor_sync(0xffffffffu, rs1, 2);
        l0 = l0 * sc0 + rs0;
        l1 = l1 * sc1 + rs1;

        // ---- out += P V (single-term fp16) ----
#pragma unroll
        for (int kg2 = 0; kg2 < 4; kg2++) {
            uint32_t pa[4];
            pa[0] = packh2(s[2 * kg2][0], s[2 * kg2][1]);
            pa[1] = packh2(s[2 * kg2][2], s[2 * kg2][3]);
            pa[2] = packh2(s[2 * kg2 + 1][0], s[2 * kg2 + 1][1]);
            pa[3] = packh2(s[2 * kg2 + 1][2], s[2 * kg2 + 1][3]);
            const int kk = kg2 * 16 + tig * 2;
#pragma unroll
            for (int nt = 0; nt < 8; nt++) {
                const __half* pb = Vth + (nt * 8 + g) * ASROW + kk;
                uint32_t bf[2] = { *(const uint32_t*)pb, *(const uint32_t*)(pb + 8) };
                mma16816(out[nt], pa, bf);
            }
        }
        __syncthreads();
    }

    // ---- write ctx (b,s,h,d) fp16 ----
    const float i0 = 1.0f / l0, i1 = 1.0f / l1;
    const int r0 = qrow0 + g, r1 = qrow0 + g + 8;
    __half* p0 = ctx + ((size_t)(b * Sq + r0) * Hh + h) * DH;
    __half* p1 = ctx + ((size_t)(b * Sq + r1) * Hh + h) * DH;
#pragma unroll
    for (int nt = 0; nt < 8; nt++) {
        const int dh = nt * 8 + tig * 2;
        *(__half2*)(p0 + dh) = __floats2half2_rn(out[nt][0] * i0, out[nt][1] * i0);
        *(__half2*)(p1 + dh) = __floats2half2_rn(out[nt][2] * i1, out[nt][3] * i1);
    }
}

// ---------------- fused add + LayerNorm (+ optional fp16 out) ----------------
__global__ __launch_bounds__(256)
void addln_kernel(const float* __restrict__ a, const float* __restrict__ b,
                  const float* __restrict__ g, const float* __restrict__ bt,
                  float* __restrict__ o, __half* __restrict__ oh) {
    __shared__ float redS[8], redQ[8], outMV[2];
    const int row = blockIdx.x;
    const int t = threadIdx.x;
    const float* ar = a + (size_t)row * Dm;
    const float* br = b + (size_t)row * Dm;

    float v[4];
    float s = 0.f, sq = 0.f;
#pragma unroll
    for (int i = 0; i < 4; i++) {
        int idx = t + i * 256;
        float x = ar[idx] + br[idx];
        v[i] = x;
        s += x;
        sq = fmaf(x, x, sq);
    }
#pragma unroll
    for (int off = 16; off; off >>= 1) {
        s += __shfl_xor_sync(0xFFFFFFFFu, s, off);
        sq += __shfl_xor_sync(0xFFFFFFFFu, sq, off);
    }
    if ((t & 31) == 0) { redS[t >> 5] = s; redQ[t >> 5] = sq; }
    __syncthreads();
    if (t < 32) {
        float s2 = (t < 8) ? redS[t] : 0.f;
        float q2 = (t < 8) ? redQ[t] : 0.f;
#pragma unroll
        for (int off = 4; off; off >>= 1) {
            s2 += __shfl_xor_sync(0xFFFFFFFFu, s2, off);
            q2 += __shfl_xor_sync(0xFFFFFFFFu, q2, off);
        }
        if (t == 0) {
            float mean = s2 * (1.0f / Dm);
            float var = q2 * (1.0f / Dm) - mean * mean;
            outMV[0] = mean;
            outMV[1] = rsqrtf(var + 1e-5f);
        }
    }
    __syncthreads();
    const float mean = outMV[0], rstd = outMV[1];
    float* orow = o + (size_t)row * Dm;
#pragma unroll
    for (int i = 0; i < 4; i++) {
        int idx = t + i * 256;
        float y = (v[i] - mean) * rstd * g[idx] + bt[idx];
        orow[idx] = y;
        if (oh) oh[(size_t)row * Dm + idx] = __float2half_rn(y);
    }
}

// ---------------- launch ----------------
extern "C" void kernel_launch(void* const* d_in, const int* in_sizes, int n_in,
                              void* d_out, int out_size) {
    const float* seq  = (const float*)d_in[0];
    const unsigned char* mask = (const unsigned char*)d_in[1];
    const float* Wqkv = (const float*)d_in[2];
    const float* bqkv = (const float*)d_in[3];
    const float* Wo   = (const float*)d_in[4];
    const float* bo   = (const float*)d_in[5];
    const float* g1   = (const float*)d_in[6];
    const float* b1   = (const float*)d_in[7];
    const float* Wi   = (const float*)d_in[8];
    const float* bi   = (const float*)d_in[9];
    const float* Wout = (const float*)d_in[10];
    const float* bout = (const float*)d_in[11];
    const float* g2   = (const float*)d_in[12];
    const float* b2   = (const float*)d_in[13];
    float* out = (float*)d_out;

    __half *seqh, *seql, *Bqkvh, *Bqkvl, *Woh, *Wol, *Wih, *Wil, *Wouth, *Woutl;
    __half *qh, *ql, *kh, *kl, *vh, *ctxh, *xh, *hh;
    float *attn, *x, *y;
    cudaGetSymbolAddress((void**)&seqh, g_seqh);   cudaGetSymbolAddress((void**)&seql, g_seql);
    cudaGetSymbolAddress((void**)&Bqkvh, g_Bqkvh); cudaGetSymbolAddress((void**)&Bqkvl, g_Bqkvl);
    cudaGetSymbolAddress((void**)&Woh, g_Woh);     cudaGetSymbolAddress((void**)&Wol, g_Wol);
    cudaGetSymbolAddress((void**)&Wih, g_Wih);     cudaGetSymbolAddress((void**)&Wil, g_Wil);
    cudaGetSymbolAddress((void**)&Wouth, g_Wouth); cudaGetSymbolAddress((void**)&Woutl, g_Woutl);
    cudaGetSymbolAddress((void**)&qh, g_qh);       cudaGetSymbolAddress((void**)&ql, g_ql);
    cudaGetSymbolAddress((void**)&kh, g_kh);       cudaGetSymbolAddress((void**)&kl, g_kl);
    cudaGetSymbolAddress((void**)&vh, g_vh);       cudaGetSymbolAddress((void**)&ctxh, g_ctxh);
    cudaGetSymbolAddress((void**)&xh, g_xh);       cudaGetSymbolAddress((void**)&hh, g_hh);
    cudaGetSymbolAddress((void**)&attn, g_attn);   cudaGetSymbolAddress((void**)&x, g_x);
    cudaGetSymbolAddress((void**)&y, g_y);

    const int SM3 = 2 * 4 * TILE_B;   // 147456
    const int SM2 = 2 * 3 * TILE_B;   // 110592
    cudaFuncSetAttribute(mma_gemm<1, 3>, cudaFuncAttributeMaxDynamicSharedMemorySize, SM3);
    cudaFuncSetAttribute(mma_gemm<0, 2>, cudaFuncAttributeMaxDynamicSharedMemorySize, SM2);
    cudaFuncSetAttribute(mma_gemm<2, 2>, cudaFuncAttributeMaxDynamicSharedMemorySize, SM2);

    // weight packing (transpose + fp16 hi/lo split)
    packW_kernel<<<dim3(192 / 32, Dm / 32, Hh), dim3(32, 8)>>>(Wqkv, Bqkvh, Bqkvl, Dm, 192);
    packW_kernel<<<dim3(Dm / 32, Dm / 32, 1), dim3(32, 8)>>>(Wo, Woh, Wol, Dm, Dm);
    packW_kernel<<<dim3(Ii / 32, Dm / 32, 1), dim3(32, 8)>>>(Wi, Wih, Wil, Dm, Ii);
    packW_kernel<<<dim3(Dm / 32, Ii / 32, 1), dim3(32, 8)>>>(Wout, Wouth, Woutl, Ii, Dm);

    // seq -> fp16 hi/lo
    split_kernel<<<(ROWS * Dm / 4 + 255) / 256, 256>>>(seq, seqh, seql, ROWS * Dm);

    // QKV projection (3-term) + scatter/scale -> q(hi/lo), k(hi/lo), v(hi)
    mma_gemm<1, 3><<<dim3(NQKV / 128, ROWS / 128), 256, SM3>>>(
        seqh, seql, Bqkvh, Bqkvl, bqkv, nullptr, qh, ql, kh, kl, vh, nullptr, Dm, NQKV);

    // tensor-core flash attention -> ctx fp16
    attn_mma<<<dim3(8, Hh, Bz), 256>>>(qh, ql, kh, kl, vh, mask, ctxh);

    // output projection (2-term)
    mma_gemm<0, 2><<<dim3(Dm / 128, ROWS / 128), 256, SM2>>>(
        ctxh, nullptr, Woh, Wol, bo, attn,
        nullptr, nullptr, nullptr, nullptr, nullptr, nullptr, Dm, Dm);

    // x = LN(seq + attn) (+ fp16 for Wi)
    addln_kernel<<<ROWS, 256>>>(seq, attn, g1, b1, x, xh);

    // h = gelu(x @ Wi + bi) (2-term) -> fp16
    mma_gemm<2, 2><<<dim3(Ii / 128, ROWS / 128), 256, SM2>>>(
        xh, nullptr, Wih, Wil, bi, nullptr,
        nullptr, nullptr, nullptr, nullptr, nullptr, hh, Dm, Ii);

    // y = h @ Wout + bout (2-term)
    mma_gemm<0, 2><<<dim3(Dm / 128, ROWS / 128), 256, SM2>>>(
        hh, nullptr, Wouth, Woutl, bout, y,
        nullptr, nullptr, nullptr, nullptr, nullptr, nullptr, Ii, Dm);

    // out = LN(x + y)
    addln_kernel<<<ROWS, 256>>>(x, y, g2, b2, out, nullptr);
}

// round 8
// speedup vs baseline: 4.5882x; 1.3836x over previous
#include <cuda_runtime.h>
#include <cuda_fp16.h>
#include <math.h>
#include <stdint.h>

#define Bz 8
#define Sq 1024
#define Dm 1024
#define Hh 16
#define DH 64
#define Ii 4096
#define NQKV 3072
#define ROWS (Bz * Sq)

// ---------------- scratch (static device memory; no allocations) ----------------
__device__ __half g_seqh[ROWS * Dm], g_seql[ROWS * Dm];
__device__ __half g_Bqkvh[NQKV * Dm], g_Bqkvl[NQKV * Dm];
__device__ __half g_Woh[Dm * Dm];
__device__ __half g_Wih[Ii * Dm];
__device__ __half g_Wouth[Dm * Ii];
__device__ __half g_qh[ROWS * Dm], g_ql[ROWS * Dm];
__device__ __half g_kh[ROWS * Dm], g_kl[ROWS * Dm];
__device__ __half g_vh[ROWS * Dm];
__device__ __half g_ctxh[ROWS * Dm];
__device__ float g_attn[ROWS * Dm];
__device__ float g_x[ROWS * Dm];
__device__ __half g_xh[ROWS * Dm];
__device__ __half g_hh[ROWS * Ii];
__device__ float g_y[ROWS * Dm];

// ---------------- helpers ----------------
__device__ __forceinline__ uint32_t smem_u32(const void* p) {
    uint32_t r;
    asm("{ .reg .u64 t; cvta.to.shared.u64 t, %1; cvt.u32.u64 %0, t; }" : "=r"(r) : "l"(p));
    return r;
}
#define CP_ASYNC16(dst, src) \
    asm volatile("cp.async.cg.shared.global [%0], [%1], 16;" :: "r"(dst), "l"(src) : "memory")
#define CP_COMMIT() asm volatile("cp.async.commit_group;" ::: "memory")
#define CP_WAIT1()  asm volatile("cp.async.wait_group 1;" ::: "memory")
#define CP_WAIT0()  asm volatile("cp.async.wait_group 0;" ::: "memory")

__device__ __forceinline__ void mma16816(float* d, const uint32_t* a, const uint32_t* b) {
    asm volatile(
        "mma.sync.aligned.m16n8k16.row.col.f32.f16.f16.f32 "
        "{%0,%1,%2,%3}, {%4,%5,%6,%7}, {%8,%9}, {%0,%1,%2,%3};"
        : "+f"(d[0]), "+f"(d[1]), "+f"(d[2]), "+f"(d[3])
        : "r"(a[0]), "r"(a[1]), "r"(a[2]), "r"(a[3]), "r"(b[0]), "r"(b[1]));
}
__device__ __forceinline__ void ldsm4(uint32_t* r, uint32_t a) {
    asm volatile("ldmatrix.sync.aligned.m8n8.x4.shared.b16 {%0,%1,%2,%3}, [%4];"
                 : "=r"(r[0]), "=r"(r[1]), "=r"(r[2]), "=r"(r[3]) : "r"(a));
}
__device__ __forceinline__ uint32_t packh2(float a, float b) {
    __half2 h = __floats2half2_rn(a, b);
    return *(uint32_t*)&h;
}

// ---------------- weight pack: transpose (K,N)->(N,K) fp16 (+ optional lo) ----------------
__global__ void packW_kernel(const float* __restrict__ w, __half* __restrict__ oh,
                             __half* __restrict__ ol, int K, int N) {
    __shared__ float t[32][33];
    const int z = blockIdx.z;
    const float* in = w + (size_t)z * K * N;
    __half* poh = oh + (size_t)z * N * K;
    __half* pol = ol ? ol + (size_t)z * N * K : nullptr;
    const int n0 = blockIdx.x * 32, k0 = blockIdx.y * 32;
    const int tx = threadIdx.x, ty = threadIdx.y;
#pragma unroll
    for (int i = 0; i < 32; i += 8)
        t[ty + i][tx] = in[(size_t)(k0 + ty + i) * N + n0 + tx];
    __syncthreads();
#pragma unroll
    for (int i = 0; i < 32; i += 8) {
        float v = t[tx][ty + i];
        __half hi = __float2half_rn(v);
        size_t o = (size_t)(n0 + ty + i) * K + k0 + tx;
        poh[o] = hi;
        if (pol) pol[o] = __float2half_rn(v - __half2float(hi));
    }
}

// ---------------- fp32 -> fp16 hi/lo ----------------
__global__ void split_kernel(const float* __restrict__ in, __half* __restrict__ oh,
                             __half* __restrict__ ol, int n) {
    int i = (blockIdx.x * 256 + threadIdx.x) * 4;
    if (i < n) {
        float4 v = *(const float4*)(in + i);
        __half h0 = __float2half_rn(v.x), h1 = __float2half_rn(v.y);
        __half h2 = __float2half_rn(v.z), h3 = __float2half_rn(v.w);
        __half2* ph = (__half2*)(oh + i);
        ph[0] = __halves2half2(h0, h1);
        ph[1] = __halves2half2(h2, h3);
        __half2* pl = (__half2*)(ol + i);
        pl[0] = __halves2half2(__float2half_rn(v.x - __half2float(h0)),
                               __float2half_rn(v.y - __half2float(h1)));
        pl[1] = __halves2half2(__float2half_rn(v.z - __half2float(h2)),
                               __float2half_rn(v.w - __half2float(h3)));
    }
}

// ---------------- mma.sync GEMM (ldmatrix fragments) ----------------
// TERMS=3: acc = Ah*Bh + Ah*Bl + Al*Bh   (A hi/lo, B hi/lo)
// TERMS=1: acc = A*B                     (both single fp16)
#define SROW 72
#define TILE_H (128 * SROW)
#define TILE_B (TILE_H * 2)            // 18432 bytes

template <int EPI, int TERMS, int OCC>
__global__ __launch_bounds__(256, OCC)
void mma_gemm(const __half* __restrict__ Ah, const __half* __restrict__ Al,
              const __half* __restrict__ Bh, const __half* __restrict__ Bl,
              const float* __restrict__ bias, float* __restrict__ Cf,
              __half* __restrict__ qh, __half* __restrict__ ql,
              __half* __restrict__ kh, __half* __restrict__ kl,
              __half* __restrict__ vh, __half* __restrict__ Oh,
              int K, int N) {
    constexpr int NTILES = (TERMS == 3) ? 4 : 2;
    constexpr int STAGE_B = NTILES * TILE_B;
    extern __shared__ char smem[];
    const uint32_t sb = smem_u32(smem);
    const int tid = threadIdx.x;
    const int w = tid >> 5, lane = tid & 31;
    const int g = lane >> 2, tig = lane & 3;
    const int quad = lane >> 3, lr = lane & 7;
    const int bm = blockIdx.y, bn = blockIdx.x;
    const int wm = (w >> 2) * 64;
    const int wn = (w & 3) * 32;

    // per-lane ldmatrix offsets (bytes)
    const uint32_t aoff = (((quad & 1) * 8 + lr) * SROW + (quad >> 1) * 8) * 2;
    const uint32_t boff = (((quad >> 1) * 8 + lr) * SROW + (quad & 1) * 8) * 2;

    const __half* gp[4];
    gp[0] = Ah + (size_t)bm * 128 * K;
    if (TERMS == 3) {
        gp[1] = Al + (size_t)bm * 128 * K;
        gp[2] = Bh + (size_t)bn * 128 * K;
        gp[3] = Bl + (size_t)bn * 128 * K;
    } else {
        gp[1] = Bh + (size_t)bn * 128 * K;
    }

    int lrow[4], lcb[4];
#pragma unroll
    for (int i = 0; i < 4; i++) { int c = tid + i * 256; lrow[i] = c >> 3; lcb[i] = c & 7; }

    float acc[4][4][4];
#pragma unroll
    for (int mi = 0; mi < 4; mi++)
#pragma unroll
        for (int ni = 0; ni < 4; ni++)
#pragma unroll
            for (int e = 0; e < 4; e++) acc[mi][ni][e] = 0.f;

    const int NT = K / 64;

    auto issue_stage = [&](int kt) {
        const uint32_t dstS = sb + (kt & 1) * STAGE_B;
#pragma unroll
        for (int t = 0; t < NTILES; t++) {
            const __half* src = gp[t] + kt * 64;
#pragma unroll
            for (int i = 0; i < 4; i++) {
                CP_ASYNC16(dstS + t * TILE_B + lrow[i] * (SROW * 2) + lcb[i] * 16,
                           src + (size_t)lrow[i] * K + lcb[i] * 8);
            }
        }
        CP_COMMIT();
    };

    issue_stage(0);

    for (int kt = 0; kt < NT; kt++) {
        if (kt + 1 < NT) { issue_stage(kt + 1); CP_WAIT1(); } else { CP_WAIT0(); }
        __syncthreads();

        const uint32_t sA  = sb + (kt & 1) * STAGE_B;
        const uint32_t sAl = sA + TILE_B;                         // TERMS==3
        const uint32_t sBh = sA + ((TERMS == 3) ? 2 : 1) * TILE_B;
        const uint32_t sBl = sA + 3 * TILE_B;                     // TERMS==3

#pragma unroll
        for (int ks = 0; ks < 4; ks++) {
            const uint32_t k0b = (uint32_t)(ks * 16) * 2;
            uint32_t ah[4][4], al[4][4], bh[4][2], bl[4][2];
#pragma unroll
            for (int mi = 0; mi < 4; mi++) {
                const uint32_t rbase = (uint32_t)((wm + mi * 16) * SROW) * 2 + k0b;
                ldsm4(ah[mi], sA + rbase + aoff);
                if (TERMS == 3) ldsm4(al[mi], sAl + rbase + aoff);
            }
#pragma unroll
            for (int np = 0; np < 2; np++) {
                const uint32_t rbase = (uint32_t)((wn + np * 16) * SROW) * 2 + k0b;
                uint32_t rr[4];
                ldsm4(rr, sBh + rbase + boff);
                bh[2 * np][0] = rr[0]; bh[2 * np][1] = rr[1];
                bh[2 * np + 1][0] = rr[2]; bh[2 * np + 1][1] = rr[3];
                if (TERMS == 3) {
                    ldsm4(rr, sBl + rbase + boff);
                    bl[2 * np][0] = rr[0]; bl[2 * np][1] = rr[1];
                    bl[2 * np + 1][0] = rr[2]; bl[2 * np + 1][1] = rr[3];
                }
            }
#pragma unroll
            for (int mi = 0; mi < 4; mi++)
#pragma unroll
                for (int ni = 0; ni < 4; ni++) {
                    mma16816(acc[mi][ni], ah[mi], bh[ni]);
                    if (TERMS == 3) {
                        mma16816(acc[mi][ni], ah[mi], bl[ni]);
                        mma16816(acc[mi][ni], al[mi], bh[ni]);
                    }
                }
        }
        __syncthreads();
    }

    // ---------------- epilogue ----------------
#pragma unroll
    for (int mi = 0; mi < 4; mi++) {
#pragma unroll
        for (int half_ = 0; half_ < 2; half_++) {
            const int row = bm * 128 + wm + mi * 16 + g + half_ * 8;
#pragma unroll
            for (int ni = 0; ni < 4; ni++) {
                const int c = bn * 128 + wn + ni * 8 + tig * 2;
                float v0 = acc[mi][ni][half_ * 2 + 0] + bias[c];
                float v1 = acc[mi][ni][half_ * 2 + 1] + bias[c + 1];
                if (EPI == 0) {
                    *(float2*)&Cf[(size_t)row * N + c] = make_float2(v0, v1);
                } else if (EPI == 2) {
                    float g0 = 0.5f * v0 * (1.0f + erff(v0 * 0.70710678118654752f));
                    float g1 = 0.5f * v1 * (1.0f + erff(v1 * 0.70710678118654752f));
                    *(__half2*)&Oh[(size_t)row * N + c] = __floats2half2_rn(g0, g1);
                } else {
                    const int h = c / 192;
                    const int e = c - h * 192;
                    const int b_ = row >> 10, s_ = row & 1023;
                    const size_t base = ((size_t)(b_ * Hh + h) * Sq + s_) * DH;
                    if (e < DH) {
                        float s0 = v0 * 8.0f, s1 = v1 * 8.0f;   // sqrt(DH)=8
                        __half h0 = __float2half_rn(s0), h1 = __float2half_rn(s1);
                        *(__half2*)&qh[base + e] = __halves2half2(h0, h1);
                        *(__half2*)&ql[base + e] =
                            __halves2half2(__float2half_rn(s0 - __half2float(h0)),
                                           __float2half_rn(s1 - __half2float(h1)));
                    } else if (e < 2 * DH) {
                        __half h0 = __float2half_rn(v0), h1 = __float2half_rn(v1);
                        *(__half2*)&kh[base + e - DH] = __halves2half2(h0, h1);
                        *(__half2*)&kl[base + e - DH] =
                            __halves2half2(__float2half_rn(v0 - __half2float(h0)),
                                           __float2half_rn(v1 - __half2float(h1)));
                    } else {
                        *(__half2*)&vh[base + e - 2 * DH] = __floats2half2_rn(v0, v1);
                    }
                }
            }
        }
    }
}

// ---------------- tensor-core flash attention ----------------
#define ASROW 72
__global__ __launch_bounds__(256, 2)
void attn_mma(const __half* __restrict__ qg, const __half* __restrict__ qlg,
              const __half* __restrict__ kg, const __half* __restrict__ klg,
              const __half* __restrict__ vg, const unsigned char* __restrict__ maskg,
              __half* __restrict__ ctx) {
    __shared__ __half Ksh[64 * ASROW];
    __shared__ __half Ksl[64 * ASROW];
    __shared__ __half Vth[64 * ASROW];
    __shared__ unsigned char Ms[64];

    const int tid = threadIdx.x;
    const int w = tid >> 5, lane = tid & 31;
    const int g = lane >> 2, tig = lane & 3;
    const int qblk = blockIdx.x, h = blockIdx.y, b = blockIdx.z;
    const size_t bh = (size_t)(b * Hh + h) * Sq;
    const int qrow0 = qblk * 128 + w * 16;

    uint32_t qfh[4][4], qfl[4][4];
#pragma unroll
    for (int ks = 0; ks < 4; ks++) {
        const int k0 = ks * 16 + tig * 2;
        const size_t r0 = (bh + qrow0 + g) * DH;
        const size_t r1 = (bh + qrow0 + g + 8) * DH;
        qfh[ks][0] = *(const uint32_t*)(qg + r0 + k0);
        qfh[ks][1] = *(const uint32_t*)(qg + r1 + k0);
        qfh[ks][2] = *(const uint32_t*)(qg + r0 + k0 + 8);
        qfh[ks][3] = *(const uint32_t*)(qg + r1 + k0 + 8);
        qfl[ks][0] = *(const uint32_t*)(qlg + r0 + k0);
        qfl[ks][1] = *(const uint32_t*)(qlg + r1 + k0);
        qfl[ks][2] = *(const uint32_t*)(qlg + r0 + k0 + 8);
        qfl[ks][3] = *(const uint32_t*)(qlg + r1 + k0 + 8);
    }

    float out[8][4];
#pragma unroll
    for (int nt = 0; nt < 8; nt++)
#pragma unroll
        for (int e = 0; e < 4; e++) out[nt][e] = 0.f;
    float m0 = -1e30f, m1 = -1e30f, l0 = 0.f, l1 = 0.f;

    for (int kt = 0; kt < 16; kt++) {
#pragma unroll
        for (int i = 0; i < 8; i++) {
            int c = tid + i * 256;
            int row = c >> 5, c2 = c & 31;
            const size_t gsrc = (bh + kt * 64 + row) * DH + c2 * 2;
            *(uint32_t*)&Ksh[row * ASROW + c2 * 2] = *(const uint32_t*)(kg + gsrc);
            *(uint32_t*)&Ksl[row * ASROW + c2 * 2] = *(const uint32_t*)(klg + gsrc);
            __half2 v2 = *(const __half2*)(vg + gsrc);
            Vth[(c2 * 2) * ASROW + row] = __low2half(v2);
            Vth[(c2 * 2 + 1) * ASROW + row] = __high2half(v2);
        }
        if (tid < 64) Ms[tid] = maskg[b * Sq + kt * 64 + tid];
        __syncthreads();

        float s[8][4];
#pragma unroll
        for (int nt = 0; nt < 8; nt++)
#pragma unroll
            for (int e = 0; e < 4; e++) s[nt][e] = 0.f;
#pragma unroll
        for (int ks = 0; ks < 4; ks++) {
            const int k0 = ks * 16 + tig * 2;
#pragma unroll
            for (int nt = 0; nt < 8; nt++) {
                const __half* pb = Ksh + (nt * 8 + g) * ASROW + k0;
                const __half* pc = Ksl + (nt * 8 + g) * ASROW + k0;
                uint32_t bhf[2] = { *(const uint32_t*)pb, *(const uint32_t*)(pb + 8) };
                uint32_t blf[2] = { *(const uint32_t*)pc, *(const uint32_t*)(pc + 8) };
                mma16816(s[nt], qfh[ks], bhf);
                mma16816(s[nt], qfl[ks], bhf);
                mma16816(s[nt], qfh[ks], blf);
            }
        }

        float mx0 = -1e30f, mx1 = -1e30f;
#pragma unroll
        for (int nt = 0; nt < 8; nt++) {
            const int col = nt * 8 + tig * 2;
            if (Ms[col])     { s[nt][0] = -1e30f; s[nt][2] = -1e30f; }
            if (Ms[col + 1]) { s[nt][1] = -1e30f; s[nt][3] = -1e30f; }
            mx0 = fmaxf(mx0, fmaxf(s[nt][0], s[nt][1]));
            mx1 = fmaxf(mx1, fmaxf(s[nt][2], s[nt][3]));
        }
        mx0 = fmaxf(mx0, __shfl_xor_sync(0xffffffffu, mx0, 1));
        mx0 = fmaxf(mx0, __shfl_xor_sync(0xffffffffu, mx0, 2));
        mx1 = fmaxf(mx1, __shfl_xor_sync(0xffffffffu, mx1, 1));
        mx1 = fmaxf(mx1, __shfl_xor_sync(0xffffffffu, mx1, 2));
        const float mn0 = fmaxf(m0, mx0), mn1 = fmaxf(m1, mx1);
        const float sc0 = __expf(m0 - mn0), sc1 = __expf(m1 - mn1);
        m0 = mn0; m1 = mn1;
        float rs0 = 0.f, rs1 = 0.f;
#pragma unroll
        for (int nt = 0; nt < 8; nt++) {
            s[nt][0] = __expf(s[nt][0] - mn0);
            s[nt][1] = __expf(s[nt][1] - mn0);
            s[nt][2] = __expf(s[nt][2] - mn1);
            s[nt][3] = __expf(s[nt][3] - mn1);
            rs0 += s[nt][0] + s[nt][1];
            rs1 += s[nt][2] + s[nt][3];
            out[nt][0] *= sc0; out[nt][1] *= sc0;
            out[nt][2] *= sc1; out[nt][3] *= sc1;
        }
        rs0 += __shfl_xor_sync(0xffffffffu, rs0, 1);
        rs0 += __shfl_xor_sync(0xffffffffu, rs0, 2);
        rs1 += __shfl_xor_sync(0xffffffffu, rs1, 1);
        rs1 += __shfl_xor_sync(0xffffffffu, rs1, 2);
        l0 = l0 * sc0 + rs0;
        l1 = l1 * sc1 + rs1;

#pragma unroll
        for (int kg2 = 0; kg2 < 4; kg2++) {
            uint32_t pa[4];
            pa[0] = packh2(s[2 * kg2][0], s[2 * kg2][1]);
            pa[1] = packh2(s[2 * kg2][2], s[2 * kg2][3]);
            pa[2] = packh2(s[2 * kg2 + 1][0], s[2 * kg2 + 1][1]);
            pa[3] = packh2(s[2 * kg2 + 1][2], s[2 * kg2 + 1][3]);
            const int kk = kg2 * 16 + tig * 2;
#pragma unroll
            for (int nt = 0; nt < 8; nt++) {
                const __half* pb = Vth + (nt * 8 + g) * ASROW + kk;
                uint32_t bf[2] = { *(const uint32_t*)pb, *(const uint32_t*)(pb + 8) };
                mma16816(out[nt], pa, bf);
            }
        }
        __syncthreads();
    }

    const float i0 = 1.0f / l0, i1 = 1.0f / l1;
    const int r0 = qrow0 + g, r1 = qrow0 + g + 8;
    __half* p0 = ctx + ((size_t)(b * Sq + r0) * Hh + h) * DH;
    __half* p1 = ctx + ((size_t)(b * Sq + r1) * Hh + h) * DH;
#pragma unroll
    for (int nt = 0; nt < 8; nt++) {
        const int dh = nt * 8 + tig * 2;
        *(__half2*)(p0 + dh) = __floats2half2_rn(out[nt][0] * i0, out[nt][1] * i0);
        *(__half2*)(p1 + dh) = __floats2half2_rn(out[nt][2] * i1, out[nt][3] * i1);
    }
}

// ---------------- fused add + LayerNorm (+ optional fp16 out) ----------------
__global__ __launch_bounds__(256)
void addln_kernel(const float* __restrict__ a, const float* __restrict__ b,
                  const float* __restrict__ g, const float* __restrict__ bt,
                  float* __restrict__ o, __half* __restrict__ oh) {
    __shared__ float redS[8], redQ[8], outMV[2];
    const int row = blockIdx.x;
    const int t = threadIdx.x;
    const float* ar = a + (size_t)row * Dm;
    const float* br = b + (size_t)row * Dm;

    float v[4];
    float s = 0.f, sq = 0.f;
#pragma unroll
    for (int i = 0; i < 4; i++) {
        int idx = t + i * 256;
        float x = ar[idx] + br[idx];
        v[i] = x;
        s += x;
        sq = fmaf(x, x, sq);
    }
#pragma unroll
    for (int off = 16; off; off >>= 1) {
        s += __shfl_xor_sync(0xFFFFFFFFu, s, off);
        sq += __shfl_xor_sync(0xFFFFFFFFu, sq, off);
    }
    if ((t & 31) == 0) { redS[t >> 5] = s; redQ[t >> 5] = sq; }
    __syncthreads();
    if (t < 32) {
        float s2 = (t < 8) ? redS[t] : 0.f;
        float q2 = (t < 8) ? redQ[t] : 0.f;
#pragma unroll
        for (int off = 4; off; off >>= 1) {
            s2 += __shfl_xor_sync(0xFFFFFFFFu, s2, off);
            q2 += __shfl_xor_sync(0xFFFFFFFFu, q2, off);
        }
        if (t == 0) {
            float mean = s2 * (1.0f / Dm);
            float var = q2 * (1.0f / Dm) - mean * mean;
            outMV[0] = mean;
            outMV[1] = rsqrtf(var + 1e-5f);
        }
    }
    __syncthreads();
    const float mean = outMV[0], rstd = outMV[1];
    float* orow = o + (size_t)row * Dm;
#pragma unroll
    for (int i = 0; i < 4; i++) {
        int idx = t + i * 256;
        float y = (v[i] - mean) * rstd * g[idx] + bt[idx];
        orow[idx] = y;
        if (oh) oh[(size_t)row * Dm + idx] = __float2half_rn(y);
    }
}

// ---------------- launch ----------------
extern "C" void kernel_launch(void* const* d_in, const int* in_sizes, int n_in,
                              void* d_out, int out_size) {
    const float* seq  = (const float*)d_in[0];
    const unsigned char* mask = (const unsigned char*)d_in[1];
    const float* Wqkv = (const float*)d_in[2];
    const float* bqkv = (const float*)d_in[3];
    const float* Wo   = (const float*)d_in[4];
    const float* bo   = (const float*)d_in[5];
    const float* g1   = (const float*)d_in[6];
    const float* b1   = (const float*)d_in[7];
    const float* Wi   = (const float*)d_in[8];
    const float* bi   = (const float*)d_in[9];
    const float* Wout = (const float*)d_in[10];
    const float* bout = (const float*)d_in[11];
    const float* g2   = (const float*)d_in[12];
    const float* b2   = (const float*)d_in[13];
    float* out = (float*)d_out;

    __half *seqh, *seql, *Bqkvh, *Bqkvl, *Woh, *Wih, *Wouth;
    __half *qh, *ql, *kh, *kl, *vh, *ctxh, *xh, *hh;
    float *attn, *x, *y;
    cudaGetSymbolAddress((void**)&seqh, g_seqh);   cudaGetSymbolAddress((void**)&seql, g_seql);
    cudaGetSymbolAddress((void**)&Bqkvh, g_Bqkvh); cudaGetSymbolAddress((void**)&Bqkvl, g_Bqkvl);
    cudaGetSymbolAddress((void**)&Woh, g_Woh);
    cudaGetSymbolAddress((void**)&Wih, g_Wih);
    cudaGetSymbolAddress((void**)&Wouth, g_Wouth);
    cudaGetSymbolAddress((void**)&qh, g_qh);       cudaGetSymbolAddress((void**)&ql, g_ql);
    cudaGetSymbolAddress((void**)&kh, g_kh);       cudaGetSymbolAddress((void**)&kl, g_kl);
    cudaGetSymbolAddress((void**)&vh, g_vh);       cudaGetSymbolAddress((void**)&ctxh, g_ctxh);
    cudaGetSymbolAddress((void**)&xh, g_xh);       cudaGetSymbolAddress((void**)&hh, g_hh);
    cudaGetSymbolAddress((void**)&attn, g_attn);   cudaGetSymbolAddress((void**)&x, g_x);
    cudaGetSymbolAddress((void**)&y, g_y);

    const int SM3 = 2 * 4 * TILE_B;   // 147456
    const int SM1 = 2 * 2 * TILE_B;   // 73728
    cudaFuncSetAttribute(mma_gemm<1, 3, 1>, cudaFuncAttributeMaxDynamicSharedMemorySize, SM3);
    cudaFuncSetAttribute(mma_gemm<0, 1, 2>, cudaFuncAttributeMaxDynamicSharedMemorySize, SM1);
    cudaFuncSetAttribute(mma_gemm<2, 1, 2>, cudaFuncAttributeMaxDynamicSharedMemorySize, SM1);

    // weight packing (transpose; QKV gets hi/lo, the rest single fp16)
    packW_kernel<<<dim3(192 / 32, Dm / 32, Hh), dim3(32, 8)>>>(Wqkv, Bqkvh, Bqkvl, Dm, 192);
    packW_kernel<<<dim3(Dm / 32, Dm / 32, 1), dim3(32, 8)>>>(Wo, Woh, nullptr, Dm, Dm);
    packW_kernel<<<dim3(Ii / 32, Dm / 32, 1), dim3(32, 8)>>>(Wi, Wih, nullptr, Dm, Ii);
    packW_kernel<<<dim3(Dm / 32, Ii / 32, 1), dim3(32, 8)>>>(Wout, Wouth, nullptr, Ii, Dm);

    // seq -> fp16 hi/lo
    split_kernel<<<(ROWS * Dm / 4 + 255) / 256, 256>>>(seq, seqh, seql, ROWS * Dm);

    // QKV projection (3-term) + scatter/scale -> q(hi/lo), k(hi/lo), v(hi)
    mma_gemm<1, 3, 1><<<dim3(NQKV / 128, ROWS / 128), 256, SM3>>>(
        seqh, seql, Bqkvh, Bqkvl, bqkv, nullptr, qh, ql, kh, kl, vh, nullptr, Dm, NQKV);

    // tensor-core flash attention -> ctx fp16
    attn_mma<<<dim3(8, Hh, Bz), 256>>>(qh, ql, kh, kl, vh, mask, ctxh);

    // output projection (1-term)
    mma_gemm<0, 1, 2><<<dim3(Dm / 128, ROWS / 128), 256, SM1>>>(
        ctxh, nullptr, Woh, nullptr, bo, attn,
        nullptr, nullptr, nullptr, nullptr, nullptr, nullptr, Dm, Dm);

    // x = LN(seq + attn) (+ fp16 for Wi)
    addln_kernel<<<ROWS, 256>>>(seq, attn, g1, b1, x, xh);

    // h = gelu(x @ Wi + bi) (1-term) -> fp16
    mma_gemm<2, 1, 2><<<dim3(Ii / 128, ROWS / 128), 256, SM1>>>(
        xh, nullptr, Wih, nullptr, bi, nullptr,
        nullptr, nullptr, nullptr, nullptr, nullptr, hh, Dm, Ii);

    // y = h @ Wout + bout (1-term)
    mma_gemm<0, 1, 2><<<dim3(Dm / 128, ROWS / 128), 256, SM1>>>(
        hh, nullptr, Wouth, nullptr, bout, y,
        nullptr, nullptr, nullptr, nullptr, nullptr, nullptr, Ii, Dm);

    // out = LN(x + y)
    addln_kernel<<<ROWS, 256>>>(x, y, g2, b2, out, nullptr);
}

// round 9
// speedup vs baseline: 4.9654x; 1.0822x over previous
#include <cuda_runtime.h>
#include <cuda_fp16.h>
#include <math.h>
#include <stdint.h>

#define Bz 8
#define Sq 1024
#define Dm 1024
#define Hh 16
#define DH 64
#define Ii 4096
#define ROWS (Bz * Sq)

// ---------------- scratch (static device memory; no allocations) ----------------
__device__ __half g_seqh[ROWS * Dm], g_seql[ROWS * Dm];
__device__ __half g_Bqkh[2048 * Dm], g_Bqkl[2048 * Dm];
__device__ __half g_Bvh[1024 * Dm];
__device__ __half g_Woh[Dm * Dm];
__device__ __half g_Wih[Ii * Dm];
__device__ __half g_Wouth[Dm * Ii];
__device__ __half g_qh[ROWS * Dm], g_ql[ROWS * Dm];
__device__ __half g_kh[ROWS * Dm], g_kl[ROWS * Dm];
__device__ __half g_vh[ROWS * Dm];
__device__ __half g_ctxh[ROWS * Dm];
__device__ float g_attn[ROWS * Dm];
__device__ float g_x[ROWS * Dm];
__device__ __half g_xh[ROWS * Dm];
__device__ __half g_hh[ROWS * Ii];
__device__ float g_y[ROWS * Dm];

// ---------------- helpers ----------------
__device__ __forceinline__ uint32_t smem_u32(const void* p) {
    uint32_t r;
    asm("{ .reg .u64 t; cvta.to.shared.u64 t, %1; cvt.u32.u64 %0, t; }" : "=r"(r) : "l"(p));
    return r;
}
#define CP_ASYNC16(dst, src) \
    asm volatile("cp.async.cg.shared.global [%0], [%1], 16;" :: "r"(dst), "l"(src) : "memory")
#define CP_COMMIT() asm volatile("cp.async.commit_group;" ::: "memory")
#define CP_WAIT1()  asm volatile("cp.async.wait_group 1;" ::: "memory")
#define CP_WAIT0()  asm volatile("cp.async.wait_group 0;" ::: "memory")

__device__ __forceinline__ void mma16816(float* d, const uint32_t* a, const uint32_t* b) {
    asm volatile(
        "mma.sync.aligned.m16n8k16.row.col.f32.f16.f16.f32 "
        "{%0,%1,%2,%3}, {%4,%5,%6,%7}, {%8,%9}, {%0,%1,%2,%3};"
        : "+f"(d[0]), "+f"(d[1]), "+f"(d[2]), "+f"(d[3])
        : "r"(a[0]), "r"(a[1]), "r"(a[2]), "r"(a[3]), "r"(b[0]), "r"(b[1]));
}
__device__ __forceinline__ void ldsm4(uint32_t* r, uint32_t a) {
    asm volatile("ldmatrix.sync.aligned.m8n8.x4.shared.b16 {%0,%1,%2,%3}, [%4];"
                 : "=r"(r[0]), "=r"(r[1]), "=r"(r[2]), "=r"(r[3]) : "r"(a));
}
__device__ __forceinline__ uint32_t packh2(float a, float b) {
    __half2 h = __floats2half2_rn(a, b);
    return *(uint32_t*)&h;
}

// ---------------- weight pack: per-head column window, transpose + fp16 (hi[/lo]) ----
// in slice z: (K, N) row-major; takes columns [ncol0, ncol0+nout) -> out rows z*nout..
__global__ void packW_kernel(const float* __restrict__ w, __half* __restrict__ oh,
                             __half* __restrict__ ol, int K, int N, int ncol0, int nout) {
    __shared__ float t[32][33];
    const int z = blockIdx.z;
    const float* in = w + (size_t)z * K * N;
    __half* poh = oh + (size_t)z * nout * K;
    __half* pol = ol ? ol + (size_t)z * nout * K : nullptr;
    const int n0 = blockIdx.x * 32, k0 = blockIdx.y * 32;
    const int tx = threadIdx.x, ty = threadIdx.y;
#pragma unroll
    for (int i = 0; i < 32; i += 8)
        t[ty + i][tx] = in[(size_t)(k0 + ty + i) * N + ncol0 + n0 + tx];
    __syncthreads();
#pragma unroll
    for (int i = 0; i < 32; i += 8) {
        float v = t[tx][ty + i];
        __half hi = __float2half_rn(v);
        size_t o = (size_t)(n0 + ty + i) * K + k0 + tx;
        poh[o] = hi;
        if (pol) pol[o] = __float2half_rn(v - __half2float(hi));
    }
}

// ---------------- fp32 -> fp16 hi/lo ----------------
__global__ void split_kernel(const float* __restrict__ in, __half* __restrict__ oh,
                             __half* __restrict__ ol, int n) {
    int i = (blockIdx.x * 256 + threadIdx.x) * 4;
    if (i < n) {
        float4 v = *(const float4*)(in + i);
        __half h0 = __float2half_rn(v.x), h1 = __float2half_rn(v.y);
        __half h2 = __float2half_rn(v.z), h3 = __float2half_rn(v.w);
        __half2* ph = (__half2*)(oh + i);
        ph[0] = __halves2half2(h0, h1);
        ph[1] = __halves2half2(h2, h3);
        __half2* pl = (__half2*)(ol + i);
        pl[0] = __halves2half2(__float2half_rn(v.x - __half2float(h0)),
                               __float2half_rn(v.y - __half2float(h1)));
        pl[1] = __halves2half2(__float2half_rn(v.z - __half2float(h2)),
                               __float2half_rn(v.w - __half2float(h3)));
    }
}

// ---------------- mma.sync GEMM (ldmatrix fragments) ----------------
// TERMS=3: acc = Ah*Bh + Ah*Bl + Al*Bh ; TERMS=1: acc = A*B
// EPI 0: Cf = v + bias[c]
// EPI 2: Oh = fp16(gelu(v + bias[c]))
// EPI 3: QK scatter (N=2048): c -> h=c>>7, e=c&127; e<64: q*8 hi/lo, else k hi/lo
// EPI 4: V write   (N=1024): c -> h=c>>6, d=c&63 -> vh fp16
#define SROW 72
#define TILE_H (128 * SROW)
#define TILE_B (TILE_H * 2)            // 18432 bytes

template <int EPI, int TERMS, int OCC>
__global__ __launch_bounds__(256, OCC)
void mma_gemm(const __half* __restrict__ Ah, const __half* __restrict__ Al,
              const __half* __restrict__ Bh, const __half* __restrict__ Bl,
              const float* __restrict__ bias, float* __restrict__ Cf,
              __half* __restrict__ qh, __half* __restrict__ ql,
              __half* __restrict__ kh, __half* __restrict__ kl,
              __half* __restrict__ vh, __half* __restrict__ Oh,
              int K, int N) {
    constexpr int NTILES = (TERMS == 3) ? 4 : 2;
    constexpr int STAGE_B = NTILES * TILE_B;
    extern __shared__ char smem[];
    const uint32_t sb = smem_u32(smem);
    const int tid = threadIdx.x;
    const int w = tid >> 5, lane = tid & 31;
    const int g = lane >> 2, tig = lane & 3;
    const int quad = lane >> 3, lr = lane & 7;
    const int bm = blockIdx.y, bn = blockIdx.x;
    const int wm = (w >> 2) * 64;
    const int wn = (w & 3) * 32;

    const uint32_t aoff = (((quad & 1) * 8 + lr) * SROW + (quad >> 1) * 8) * 2;
    const uint32_t boff = (((quad >> 1) * 8 + lr) * SROW + (quad & 1) * 8) * 2;

    const __half* gp[4];
    gp[0] = Ah + (size_t)bm * 128 * K;
    if (TERMS == 3) {
        gp[1] = Al + (size_t)bm * 128 * K;
        gp[2] = Bh + (size_t)bn * 128 * K;
        gp[3] = Bl + (size_t)bn * 128 * K;
    } else {
        gp[1] = Bh + (size_t)bn * 128 * K;
    }

    int lrow[4], lcb[4];
#pragma unroll
    for (int i = 0; i < 4; i++) { int c = tid + i * 256; lrow[i] = c >> 3; lcb[i] = c & 7; }

    float acc[4][4][4];
#pragma unroll
    for (int mi = 0; mi < 4; mi++)
#pragma unroll
        for (int ni = 0; ni < 4; ni++)
#pragma unroll
            for (int e = 0; e < 4; e++) acc[mi][ni][e] = 0.f;

    const int NT = K / 64;

    auto issue_stage = [&](int kt) {
        const uint32_t dstS = sb + (kt & 1) * STAGE_B;
#pragma unroll
        for (int t = 0; t < NTILES; t++) {
            const __half* src = gp[t] + kt * 64;
#pragma unroll
            for (int i = 0; i < 4; i++) {
                CP_ASYNC16(dstS + t * TILE_B + lrow[i] * (SROW * 2) + lcb[i] * 16,
                           src + (size_t)lrow[i] * K + lcb[i] * 8);
            }
        }
        CP_COMMIT();
    };

    issue_stage(0);

    for (int kt = 0; kt < NT; kt++) {
        if (kt + 1 < NT) { issue_stage(kt + 1); CP_WAIT1(); } else { CP_WAIT0(); }
        __syncthreads();

        const uint32_t sA  = sb + (kt & 1) * STAGE_B;
        const uint32_t sAl = sA + TILE_B;
        const uint32_t sBh = sA + ((TERMS == 3) ? 2 : 1) * TILE_B;
        const uint32_t sBl = sA + 3 * TILE_B;

#pragma unroll
        for (int ks = 0; ks < 4; ks++) {
            const uint32_t k0b = (uint32_t)(ks * 16) * 2;
            uint32_t ah[4][4], al[4][4], bh[4][2], bl[4][2];
#pragma unroll
            for (int mi = 0; mi < 4; mi++) {
                const uint32_t rbase = (uint32_t)((wm + mi * 16) * SROW) * 2 + k0b;
                ldsm4(ah[mi], sA + rbase + aoff);
                if (TERMS == 3) ldsm4(al[mi], sAl + rbase + aoff);
            }
#pragma unroll
            for (int np = 0; np < 2; np++) {
                const uint32_t rbase = (uint32_t)((wn + np * 16) * SROW) * 2 + k0b;
                uint32_t rr[4];
                ldsm4(rr, sBh + rbase + boff);
                bh[2 * np][0] = rr[0]; bh[2 * np][1] = rr[1];
                bh[2 * np + 1][0] = rr[2]; bh[2 * np + 1][1] = rr[3];
                if (TERMS == 3) {
                    ldsm4(rr, sBl + rbase + boff);
                    bl[2 * np][0] = rr[0]; bl[2 * np][1] = rr[1];
                    bl[2 * np + 1][0] = rr[2]; bl[2 * np + 1][1] = rr[3];
                }
            }
#pragma unroll
            for (int mi = 0; mi < 4; mi++)
#pragma unroll
                for (int ni = 0; ni < 4; ni++) {
                    mma16816(acc[mi][ni], ah[mi], bh[ni]);
                    if (TERMS == 3) {
                        mma16816(acc[mi][ni], ah[mi], bl[ni]);
                        mma16816(acc[mi][ni], al[mi], bh[ni]);
                    }
                }
        }
        __syncthreads();
    }

    // ---------------- epilogue ----------------
#pragma unroll
    for (int mi = 0; mi < 4; mi++) {
#pragma unroll
        for (int half_ = 0; half_ < 2; half_++) {
            const int row = bm * 128 + wm + mi * 16 + g + half_ * 8;
#pragma unroll
            for (int ni = 0; ni < 4; ni++) {
                const int c = bn * 128 + wn + ni * 8 + tig * 2;
                float v0 = acc[mi][ni][half_ * 2 + 0];
                float v1 = acc[mi][ni][half_ * 2 + 1];
                if (EPI == 0) {
                    v0 += bias[c]; v1 += bias[c + 1];
                    *(float2*)&Cf[(size_t)row * N + c] = make_float2(v0, v1);
                } else if (EPI == 2) {
                    v0 += bias[c]; v1 += bias[c + 1];
                    float g0 = 0.5f * v0 * (1.0f + erff(v0 * 0.70710678118654752f));
                    float g1 = 0.5f * v1 * (1.0f + erff(v1 * 0.70710678118654752f));
                    *(__half2*)&Oh[(size_t)row * N + c] = __floats2half2_rn(g0, g1);
                } else if (EPI == 3) {
                    const int h = c >> 7;
                    const int e = c & 127;
                    v0 += bias[h * 192 + e]; v1 += bias[h * 192 + e + 1];
                    const int b_ = row >> 10, s_ = row & 1023;
                    const size_t base = ((size_t)(b_ * Hh + h) * Sq + s_) * DH;
                    if (e < DH) {
                        float s0 = v0 * 8.0f, s1 = v1 * 8.0f;   // sqrt(DH)=8
                        __half h0 = __float2half_rn(s0), h1 = __float2half_rn(s1);
                        *(__half2*)&qh[base + e] = __halves2half2(h0, h1);
                        *(__half2*)&ql[base + e] =
                            __halves2half2(__float2half_rn(s0 - __half2float(h0)),
                                           __float2half_rn(s1 - __half2float(h1)));
                    } else {
                        __half h0 = __float2half_rn(v0), h1 = __float2half_rn(v1);
                        *(__half2*)&kh[base + e - DH] = __halves2half2(h0, h1);
                        *(__half2*)&kl[base + e - DH] =
                            __halves2half2(__float2half_rn(v0 - __half2float(h0)),
                                           __float2half_rn(v1 - __half2float(h1)));
                    }
                } else {   // EPI == 4: V
                    const int h = c >> 6;
                    const int d = c & 63;
                    v0 += bias[h * 192 + 128 + d]; v1 += bias[h * 192 + 128 + d + 1];
                    const int b_ = row >> 10, s_ = row & 1023;
                    const size_t base = ((size_t)(b_ * Hh + h) * Sq + s_) * DH;
                    *(__half2*)&vh[base + d] = __floats2half2_rn(v0, v1);
                }
            }
        }
    }
}

// ---------------- tensor-core flash attention ----------------
#define ASROW 72
__global__ __launch_bounds__(256, 2)
void attn_mma(const __half* __restrict__ qg, const __half* __restrict__ qlg,
              const __half* __restrict__ kg, const __half* __restrict__ klg,
              const __half* __restrict__ vg, const unsigned char* __restrict__ maskg,
              __half* __restrict__ ctx) {
    __shared__ __half Ksh[64 * ASROW];
    __shared__ __half Ksl[64 * ASROW];
    __shared__ __half Vth[64 * ASROW];
    __shared__ unsigned char Ms[64];

    const int tid = threadIdx.x;
    const int w = tid >> 5, lane = tid & 31;
    const int g = lane >> 2, tig = lane & 3;
    const int qblk = blockIdx.x, h = blockIdx.y, b = blockIdx.z;
    const size_t bh = (size_t)(b * Hh + h) * Sq;
    const int qrow0 = qblk * 128 + w * 16;

    uint32_t qfh[4][4], qfl[4][4];
#pragma unroll
    for (int ks = 0; ks < 4; ks++) {
        const int k0 = ks * 16 + tig * 2;
        const size_t r0 = (bh + qrow0 + g) * DH;
        const size_t r1 = (bh + qrow0 + g + 8) * DH;
        qfh[ks][0] = *(const uint32_t*)(qg + r0 + k0);
        qfh[ks][1] = *(const uint32_t*)(qg + r1 + k0);
        qfh[ks][2] = *(const uint32_t*)(qg + r0 + k0 + 8);
        qfh[ks][3] = *(const uint32_t*)(qg + r1 + k0 + 8);
        qfl[ks][0] = *(const uint32_t*)(qlg + r0 + k0);
        qfl[ks][1] = *(const uint32_t*)(qlg + r1 + k0);
        qfl[ks][2] = *(const uint32_t*)(qlg + r0 + k0 + 8);
        qfl[ks][3] = *(const uint32_t*)(qlg + r1 + k0 + 8);
    }

    float out[8][4];
#pragma unroll
    for (int nt = 0; nt < 8; nt++)
#pragma unroll
        for (int e = 0; e < 4; e++) out[nt][e] = 0.f;
    float m0 = -1e30f, m1 = -1e30f, l0 = 0.f, l1 = 0.f;

    for (int kt = 0; kt < 16; kt++) {
#pragma unroll
        for (int i = 0; i < 8; i++) {
            int c = tid + i * 256;
            int row = c >> 5, c2 = c & 31;
            const size_t gsrc = (bh + kt * 64 + row) * DH + c2 * 2;
            *(uint32_t*)&Ksh[row * ASROW + c2 * 2] = *(const uint32_t*)(kg + gsrc);
            *(uint32_t*)&Ksl[row * ASROW + c2 * 2] = *(const uint32_t*)(klg + gsrc);
            __half2 v2 = *(const __half2*)(vg + gsrc);
            Vth[(c2 * 2) * ASROW + row] = __low2half(v2);
            Vth[(c2 * 2 + 1) * ASROW + row] = __high2half(v2);
        }
        if (tid < 64) Ms[tid] = maskg[b * Sq + kt * 64 + tid];
        __syncthreads();

        float s[8][4];
#pragma unroll
        for (int nt = 0; nt < 8; nt++)
#pragma unroll
            for (int e = 0; e < 4; e++) s[nt][e] = 0.f;
#pragma unroll
        for (int ks = 0; ks < 4; ks++) {
            const int k0 = ks * 16 + tig * 2;
#pragma unroll
            for (int nt = 0; nt < 8; nt++) {
                const __half* pb = Ksh + (nt * 8 + g) * ASROW + k0;
                const __half* pc = Ksl + (nt * 8 + g) * ASROW + k0;
                uint32_t bhf[2] = { *(const uint32_t*)pb, *(const uint32_t*)(pb + 8) };
                uint32_t blf[2] = { *(const uint32_t*)pc, *(const uint32_t*)(pc + 8) };
                mma16816(s[nt], qfh[ks], bhf);
                mma16816(s[nt], qfl[ks], bhf);
                mma16816(s[nt], qfh[ks], blf);
            }
        }

        float mx0 = -1e30f, mx1 = -1e30f;
#pragma unroll
        for (int nt = 0; nt < 8; nt++) {
            const int col = nt * 8 + tig * 2;
            if (Ms[col])     { s[nt][0] = -1e30f; s[nt][2] = -1e30f; }
            if (Ms[col + 1]) { s[nt][1] = -1e30f; s[nt][3] = -1e30f; }
            mx0 = fmaxf(mx0, fmaxf(s[nt][0], s[nt][1]));
            mx1 = fmaxf(mx1, fmaxf(s[nt][2], s[nt][3]));
        }
        mx0 = fmaxf(mx0, __shfl_xor_sync(0xffffffffu, mx0, 1));
        mx0 = fmaxf(mx0, __shfl_xor_sync(0xffffffffu, mx0, 2));
        mx1 = fmaxf(mx1, __shfl_xor_sync(0xffffffffu, mx1, 1));
        mx1 = fmaxf(mx1, __shfl_xor_sync(0xffffffffu, mx1, 2));
        const float mn0 = fmaxf(m0, mx0), mn1 = fmaxf(m1, mx1);
        const float sc0 = __expf(m0 - mn0), sc1 = __expf(m1 - mn1);
        m0 = mn0; m1 = mn1;
        float rs0 = 0.f, rs1 = 0.f;
#pragma unroll
        for (int nt = 0; nt < 8; nt++) {
            s[nt][0] = __expf(s[nt][0] - mn0);
            s[nt][1] = __expf(s[nt][1] - mn0);
            s[nt][2] = __expf(s[nt][2] - mn1);
            s[nt][3] = __expf(s[nt][3] - mn1);
            rs0 += s[nt][0] + s[nt][1];
            rs1 += s[nt][2] + s[nt][3];
            out[nt][0] *= sc0; out[nt][1] *= sc0;
            out[nt][2] *= sc1; out[nt][3] *= sc1;
        }
        rs0 += __shfl_xor_sync(0xffffffffu, rs0, 1);
        rs0 += __shfl_xor_sync(0xffffffffu, rs0, 2);
        rs1 += __shfl_xor_sync(0xffffffffu, rs1, 1);
        rs1 += __shfl_xor_sync(0xffffffffu, rs1, 2);
        l0 = l0 * sc0 + rs0;
        l1 = l1 * sc1 + rs1;

#pragma unroll
        for (int kg2 = 0; kg2 < 4; kg2++) {
            uint32_t pa[4];
            pa[0] = packh2(s[2 * kg2][0], s[2 * kg2][1]);
            pa[1] = packh2(s[2 * kg2][2], s[2 * kg2][3]);
            pa[2] = packh2(s[2 * kg2 + 1][0], s[2 * kg2 + 1][1]);
            pa[3] = packh2(s[2 * kg2 + 1][2], s[2 * kg2 + 1][3]);
            const int kk = kg2 * 16 + tig * 2;
#pragma unroll
            for (int nt = 0; nt < 8; nt++) {
                const __half* pb = Vth + (nt * 8 + g) * ASROW + kk;
                uint32_t bf[2] = { *(const uint32_t*)pb, *(const uint32_t*)(pb + 8) };
                mma16816(out[nt], pa, bf);
            }
        }
        __syncthreads();
    }

    const float i0 = 1.0f / l0, i1 = 1.0f / l1;
    const int r0 = qrow0 + g, r1 = qrow0 + g + 8;
    __half* p0 = ctx + ((size_t)(b * Sq + r0) * Hh + h) * DH;
    __half* p1 = ctx + ((size_t)(b * Sq + r1) * Hh + h) * DH;
#pragma unroll
    for (int nt = 0; nt < 8; nt++) {
        const int dh = nt * 8 + tig * 2;
        *(__half2*)(p0 + dh) = __floats2half2_rn(out[nt][0] * i0, out[nt][1] * i0);
        *(__half2*)(p1 + dh) = __floats2half2_rn(out[nt][2] * i1, out[nt][3] * i1);
    }
}

// ---------------- fused add + LayerNorm (+ optional fp16 out) ----------------
__global__ __launch_bounds__(256)
void addln_kernel(const float* __restrict__ a, const float* __restrict__ b,
                  const float* __restrict__ g, const float* __restrict__ bt,
                  float* __restrict__ o, __half* __restrict__ oh) {
    __shared__ float redS[8], redQ[8], outMV[2];
    const int row = blockIdx.x;
    const int t = threadIdx.x;
    const float* ar = a + (size_t)row * Dm;
    const float* br = b + (size_t)row * Dm;

    float v[4];
    float s = 0.f, sq = 0.f;
#pragma unroll
    for (int i = 0; i < 4; i++) {
        int idx = t + i * 256;
        float x = ar[idx] + br[idx];
        v[i] = x;
        s += x;
        sq = fmaf(x, x, sq);
    }
#pragma unroll
    for (int off = 16; off; off >>= 1) {
        s += __shfl_xor_sync(0xFFFFFFFFu, s, off);
        sq += __shfl_xor_sync(0xFFFFFFFFu, sq, off);
    }
    if ((t & 31) == 0) { redS[t >> 5] = s; redQ[t >> 5] = sq; }
    __syncthreads();
    if (t < 32) {
        float s2 = (t < 8) ? redS[t] : 0.f;
        float q2 = (t < 8) ? redQ[t] : 0.f;
#pragma unroll
        for (int off = 4; off; off >>= 1) {
            s2 += __shfl_xor_sync(0xFFFFFFFFu, s2, off);
            q2 += __shfl_xor_sync(0xFFFFFFFFu, q2, off);
        }
        if (t == 0) {
            float mean = s2 * (1.0f / Dm);
            float var = q2 * (1.0f / Dm) - mean * mean;
            outMV[0] = mean;
            outMV[1] = rsqrtf(var + 1e-5f);
        }
    }
    __syncthreads();
    const float mean = outMV[0], rstd = outMV[1];
    float* orow = o + (size_t)row * Dm;
#pragma unroll
    for (int i = 0; i < 4; i++) {
        int idx = t + i * 256;
        float y = (v[i] - mean) * rstd * g[idx] + bt[idx];
        orow[idx] = y;
        if (oh) oh[(size_t)row * Dm + idx] = __float2half_rn(y);
    }
}

// ---------------- launch ----------------
extern "C" void kernel_launch(void* const* d_in, const int* in_sizes, int n_in,
                              void* d_out, int out_size) {
    const float* seq  = (const float*)d_in[0];
    const unsigned char* mask = (const unsigned char*)d_in[1];
    const float* Wqkv = (const float*)d_in[2];
    const float* bqkv = (const float*)d_in[3];
    const float* Wo   = (const float*)d_in[4];
    const float* bo   = (const float*)d_in[5];
    const float* g1   = (const float*)d_in[6];
    const float* b1   = (const float*)d_in[7];
    const float* Wi   = (const float*)d_in[8];
    const float* bi   = (const float*)d_in[9];
    const float* Wout = (const float*)d_in[10];
    const float* bout = (const float*)d_in[11];
    const float* g2   = (const float*)d_in[12];
    const float* b2   = (const float*)d_in[13];
    float* out = (float*)d_out;

    __half *seqh, *seql, *Bqkh, *Bqkl, *Bvh, *Woh, *Wih, *Wouth;
    __half *qh, *ql, *kh, *kl, *vh, *ctxh, *xh, *hh;
    float *attn, *x, *y;
    cudaGetSymbolAddress((void**)&seqh, g_seqh);   cudaGetSymbolAddress((void**)&seql, g_seql);
    cudaGetSymbolAddress((void**)&Bqkh, g_Bqkh);   cudaGetSymbolAddress((void**)&Bqkl, g_Bqkl);
    cudaGetSymbolAddress((void**)&Bvh, g_Bvh);
    cudaGetSymbolAddress((void**)&Woh, g_Woh);
    cudaGetSymbolAddress((void**)&Wih, g_Wih);
    cudaGetSymbolAddress((void**)&Wouth, g_Wouth);
    cudaGetSymbolAddress((void**)&qh, g_qh);       cudaGetSymbolAddress((void**)&ql, g_ql);
    cudaGetSymbolAddress((void**)&kh, g_kh);       cudaGetSymbolAddress((void**)&kl, g_kl);
    cudaGetSymbolAddress((void**)&vh, g_vh);       cudaGetSymbolAddress((void**)&ctxh, g_ctxh);
    cudaGetSymbolAddress((void**)&xh, g_xh);       cudaGetSymbolAddress((void**)&hh, g_hh);
    cudaGetSymbolAddress((void**)&attn, g_attn);   cudaGetSymbolAddress((void**)&x, g_x);
    cudaGetSymbolAddress((void**)&y, g_y);

    const int SM3 = 2 * 4 * TILE_B;   // 147456
    const int SM1 = 2 * 2 * TILE_B;   // 73728
    cudaFuncSetAttribute(mma_gemm<3, 3, 1>, cudaFuncAttributeMaxDynamicSharedMemorySize, SM3);
    cudaFuncSetAttribute(mma_gemm<4, 1, 2>, cudaFuncAttributeMaxDynamicSharedMemorySize, SM1);
    cudaFuncSetAttribute(mma_gemm<0, 1, 2>, cudaFuncAttributeMaxDynamicSharedMemorySize, SM1);
    cudaFuncSetAttribute(mma_gemm<2, 1, 2>, cudaFuncAttributeMaxDynamicSharedMemorySize, SM1);

    // weight packing:
    // QK columns [0,128) per head -> Bqk (2048 rows, hi/lo); V columns [128,192) -> Bv (1024 rows)
    packW_kernel<<<dim3(4, 32, Hh), dim3(32, 8)>>>(Wqkv, Bqkh, Bqkl, Dm, 192, 0, 128);
    packW_kernel<<<dim3(2, 32, Hh), dim3(32, 8)>>>(Wqkv, Bvh, nullptr, Dm, 192, 128, 64);
    packW_kernel<<<dim3(Dm / 32, Dm / 32, 1), dim3(32, 8)>>>(Wo, Woh, nullptr, Dm, Dm, 0, Dm);
    packW_kernel<<<dim3(Ii / 32, Dm / 32, 1), dim3(32, 8)>>>(Wi, Wih, nullptr, Dm, Ii, 0, Ii);
    packW_kernel<<<dim3(Dm / 32, Ii / 32, 1), dim3(32, 8)>>>(Wout, Wouth, nullptr, Ii, Dm, 0, Dm);

    // seq -> fp16 hi/lo
    split_kernel<<<(ROWS * Dm / 4 + 255) / 256, 256>>>(seq, seqh, seql, ROWS * Dm);

    // QK projection (3-term) -> q(hi/lo)*8, k(hi/lo)
    mma_gemm<3, 3, 1><<<dim3(2048 / 128, ROWS / 128), 256, SM3>>>(
        seqh, seql, Bqkh, Bqkl, bqkv, nullptr, qh, ql, kh, kl, nullptr, nullptr, Dm, 2048);

    // V projection (1-term) -> v fp16
    mma_gemm<4, 1, 2><<<dim3(1024 / 128, ROWS / 128), 256, SM1>>>(
        seqh, nullptr, Bvh, nullptr, bqkv, nullptr,
        nullptr, nullptr, nullptr, nullptr, vh, nullptr, Dm, 1024);

    // tensor-core flash attention -> ctx fp16
    attn_mma<<<dim3(8, Hh, Bz), 256>>>(qh, ql, kh, kl, vh, mask, ctxh);

    // output projection (1-term)
    mma_gemm<0, 1, 2><<<dim3(Dm / 128, ROWS / 128), 256, SM1>>>(
        ctxh, nullptr, Woh, nullptr, bo, attn,
        nullptr, nullptr, nullptr, nullptr, nullptr, nullptr, Dm, Dm);

    // x = LN(seq + attn) (+ fp16 for Wi)
    addln_kernel<<<ROWS, 256>>>(seq, attn, g1, b1, x, xh);

    // h = gelu(x @ Wi + bi) (1-term) -> fp16
    mma_gemm<2, 1, 2><<<dim3(Ii / 128, ROWS / 128), 256, SM1>>>(
        xh, nullptr, Wih, nullptr, bi, nullptr,
        nullptr, nullptr, nullptr, nullptr, nullptr, hh, Dm, Ii);

    // y = h @ Wout + bout (1-term)
    mma_gemm<0, 1, 2><<<dim3(Dm / 128, ROWS / 128), 256, SM1>>>(
        hh, nullptr, Wouth, nullptr, bout, y,
        nullptr, nullptr, nullptr, nullptr, nullptr, nullptr, Ii, Dm);

    // out = LN(x + y)
    addln_kernel<<<ROWS, 256>>>(x, y, g2, b2, out, nullptr);
}

// round 10
// speedup vs baseline: 5.3843x; 1.0844x over previous
#include <cuda_runtime.h>
#include <cuda_fp16.h>
#include <math.h>
#include <stdint.h>

#define Bz 8
#define Sq 1024
#define Dm 1024
#define Hh 16
#define DH 64
#define Ii 4096
#define ROWS (Bz * Sq)

// ---------------- scratch (static device memory; no allocations) ----------------
__device__ __half g_seqh[ROWS * Dm], g_seql[ROWS * Dm];
__device__ __half g_Bqkh[2048 * Dm], g_Bqkl[2048 * Dm];
__device__ __half g_Bvh[1024 * Dm];
__device__ __half g_Woh[Dm * Dm];
__device__ __half g_Wih[Ii * Dm];
__device__ __half g_Wouth[Dm * Ii];
__device__ __half g_qh[ROWS * Dm], g_ql[ROWS * Dm];
__device__ __half g_kh[ROWS * Dm], g_kl[ROWS * Dm];
__device__ __half g_vh[ROWS * Dm];
__device__ __half g_ctxh[ROWS * Dm];
__device__ float g_attn[ROWS * Dm];
__device__ float g_x[ROWS * Dm];
__device__ __half g_xh[ROWS * Dm];
__device__ __half g_hh[ROWS * Ii];
__device__ float g_y[ROWS * Dm];

// ---------------- helpers ----------------
__device__ __forceinline__ uint32_t smem_u32(const void* p) {
    uint32_t r;
    asm("{ .reg .u64 t; cvta.to.shared.u64 t, %1; cvt.u32.u64 %0, t; }" : "=r"(r) : "l"(p));
    return r;
}
#define CP_ASYNC16(dst, src) \
    asm volatile("cp.async.cg.shared.global [%0], [%1], 16;" :: "r"(dst), "l"(src) : "memory")
#define CP_COMMIT() asm volatile("cp.async.commit_group;" ::: "memory")
#define CP_WAIT1()  asm volatile("cp.async.wait_group 1;" ::: "memory")
#define CP_WAIT0()  asm volatile("cp.async.wait_group 0;" ::: "memory")

__device__ __forceinline__ void mma16816(float* d, const uint32_t* a, const uint32_t* b) {
    asm volatile(
        "mma.sync.aligned.m16n8k16.row.col.f32.f16.f16.f32 "
        "{%0,%1,%2,%3}, {%4,%5,%6,%7}, {%8,%9}, {%0,%1,%2,%3};"
        : "+f"(d[0]), "+f"(d[1]), "+f"(d[2]), "+f"(d[3])
        : "r"(a[0]), "r"(a[1]), "r"(a[2]), "r"(a[3]), "r"(b[0]), "r"(b[1]));
}
__device__ __forceinline__ void ldsm4(uint32_t* r, uint32_t a) {
    asm volatile("ldmatrix.sync.aligned.m8n8.x4.shared.b16 {%0,%1,%2,%3}, [%4];"
                 : "=r"(r[0]), "=r"(r[1]), "=r"(r[2]), "=r"(r[3]) : "r"(a));
}
__device__ __forceinline__ void ldsm4t(uint32_t* r, uint32_t a) {
    asm volatile("ldmatrix.sync.aligned.m8n8.x4.trans.shared.b16 {%0,%1,%2,%3}, [%4];"
                 : "=r"(r[0]), "=r"(r[1]), "=r"(r[2]), "=r"(r[3]) : "r"(a));
}
__device__ __forceinline__ uint32_t packh2(float a, float b) {
    __half2 h = __floats2half2_rn(a, b);
    return *(uint32_t*)&h;
}

// ---------------- weight pack: per-head column window, transpose + fp16 (hi[/lo]) ----
__global__ void packW_kernel(const float* __restrict__ w, __half* __restrict__ oh,
                             __half* __restrict__ ol, int K, int N, int ncol0, int nout) {
    __shared__ float t[32][33];
    const int z = blockIdx.z;
    const float* in = w + (size_t)z * K * N;
    __half* poh = oh + (size_t)z * nout * K;
    __half* pol = ol ? ol + (size_t)z * nout * K : nullptr;
    const int n0 = blockIdx.x * 32, k0 = blockIdx.y * 32;
    const int tx = threadIdx.x, ty = threadIdx.y;
#pragma unroll
    for (int i = 0; i < 32; i += 8)
        t[ty + i][tx] = in[(size_t)(k0 + ty + i) * N + ncol0 + n0 + tx];
    __syncthreads();
#pragma unroll
    for (int i = 0; i < 32; i += 8) {
        float v = t[tx][ty + i];
        __half hi = __float2half_rn(v);
        size_t o = (size_t)(n0 + ty + i) * K + k0 + tx;
        poh[o] = hi;
        if (pol) pol[o] = __float2half_rn(v - __half2float(hi));
    }
}

// ---------------- fp32 -> fp16 hi/lo ----------------
__global__ void split_kernel(const float* __restrict__ in, __half* __restrict__ oh,
                             __half* __restrict__ ol, int n) {
    int i = (blockIdx.x * 256 + threadIdx.x) * 4;
    if (i < n) {
        float4 v = *(const float4*)(in + i);
        __half h0 = __float2half_rn(v.x), h1 = __float2half_rn(v.y);
        __half h2 = __float2half_rn(v.z), h3 = __float2half_rn(v.w);
        __half2* ph = (__half2*)(oh + i);
        ph[0] = __halves2half2(h0, h1);
        ph[1] = __halves2half2(h2, h3);
        __half2* pl = (__half2*)(ol + i);
        pl[0] = __halves2half2(__float2half_rn(v.x - __half2float(h0)),
                               __float2half_rn(v.y - __half2float(h1)));
        pl[1] = __halves2half2(__float2half_rn(v.z - __half2float(h2)),
                               __float2half_rn(v.w - __half2float(h3)));
    }
}

// ---------------- mma.sync GEMM (ldmatrix fragments) ----------------
// TERMS=3: acc = Ah*Bh + Ah*Bl + Al*Bh ; TERMS=1: acc = A*B
// EPI 0: Cf = v + bias[c]
// EPI 2: Oh = fp16(gelu(v + bias[c]))
// EPI 3: QK scatter (N=2048): c -> h=c>>7, e=c&127; e<64: q*8 hi/lo, else k hi/lo
// EPI 4: V write   (N=1024): c -> h=c>>6, d=c&63 -> vh fp16
#define SROW 72
#define TILE_H (128 * SROW)
#define TILE_B (TILE_H * 2)            // 18432 bytes

template <int EPI, int TERMS, int OCC>
__global__ __launch_bounds__(256, OCC)
void mma_gemm(const __half* __restrict__ Ah, const __half* __restrict__ Al,
              const __half* __restrict__ Bh, const __half* __restrict__ Bl,
              const float* __restrict__ bias, float* __restrict__ Cf,
              __half* __restrict__ qh, __half* __restrict__ ql,
              __half* __restrict__ kh, __half* __restrict__ kl,
              __half* __restrict__ vh, __half* __restrict__ Oh,
              int K, int N) {
    constexpr int NTILES = (TERMS == 3) ? 4 : 2;
    constexpr int STAGE_B = NTILES * TILE_B;
    extern __shared__ char smem[];
    const uint32_t sb = smem_u32(smem);
    const int tid = threadIdx.x;
    const int w = tid >> 5, lane = tid & 31;
    const int g = lane >> 2, tig = lane & 3;
    const int quad = lane >> 3, lr = lane & 7;
    const int bm = blockIdx.y, bn = blockIdx.x;
    const int wm = (w >> 2) * 64;
    const int wn = (w & 3) * 32;

    const uint32_t aoff = (((quad & 1) * 8 + lr) * SROW + (quad >> 1) * 8) * 2;
    const uint32_t boff = (((quad >> 1) * 8 + lr) * SROW + (quad & 1) * 8) * 2;

    const __half* gp[4];
    gp[0] = Ah + (size_t)bm * 128 * K;
    if (TERMS == 3) {
        gp[1] = Al + (size_t)bm * 128 * K;
        gp[2] = Bh + (size_t)bn * 128 * K;
        gp[3] = Bl + (size_t)bn * 128 * K;
    } else {
        gp[1] = Bh + (size_t)bn * 128 * K;
    }

    int lrow[4], lcb[4];
#pragma unroll
    for (int i = 0; i < 4; i++) { int c = tid + i * 256; lrow[i] = c >> 3; lcb[i] = c & 7; }

    float acc[4][4][4];
#pragma unroll
    for (int mi = 0; mi < 4; mi++)
#pragma unroll
        for (int ni = 0; ni < 4; ni++)
#pragma unroll
            for (int e = 0; e < 4; e++) acc[mi][ni][e] = 0.f;

    const int NT = K / 64;

    auto issue_stage = [&](int kt) {
        const uint32_t dstS = sb + (kt & 1) * STAGE_B;
#pragma unroll
        for (int t = 0; t < NTILES; t++) {
            const __half* src = gp[t] + kt * 64;
#pragma unroll
            for (int i = 0; i < 4; i++) {
                CP_ASYNC16(dstS + t * TILE_B + lrow[i] * (SROW * 2) + lcb[i] * 16,
                           src + (size_t)lrow[i] * K + lcb[i] * 8);
            }
        }
        CP_COMMIT();
    };

    issue_stage(0);

    for (int kt = 0; kt < NT; kt++) {
        if (kt + 1 < NT) { issue_stage(kt + 1); CP_WAIT1(); } else { CP_WAIT0(); }
        __syncthreads();

        const uint32_t sA  = sb + (kt & 1) * STAGE_B;
        const uint32_t sAl = sA + TILE_B;
        const uint32_t sBh = sA + ((TERMS == 3) ? 2 : 1) * TILE_B;
        const uint32_t sBl = sA + 3 * TILE_B;

#pragma unroll
        for (int ks = 0; ks < 4; ks++) {
            const uint32_t k0b = (uint32_t)(ks * 16) * 2;
            uint32_t ah[4][4], al[4][4], bh[4][2], bl[4][2];
#pragma unroll
            for (int mi = 0; mi < 4; mi++) {
                const uint32_t rbase = (uint32_t)((wm + mi * 16) * SROW) * 2 + k0b;
                ldsm4(ah[mi], sA + rbase + aoff);
                if (TERMS == 3) ldsm4(al[mi], sAl + rbase + aoff);
            }
#pragma unroll
            for (int np = 0; np < 2; np++) {
                const uint32_t rbase = (uint32_t)((wn + np * 16) * SROW) * 2 + k0b;
                uint32_t rr[4];
                ldsm4(rr, sBh + rbase + boff);
                bh[2 * np][0] = rr[0]; bh[2 * np][1] = rr[1];
                bh[2 * np + 1][0] = rr[2]; bh[2 * np + 1][1] = rr[3];
                if (TERMS == 3) {
                    ldsm4(rr, sBl + rbase + boff);
                    bl[2 * np][0] = rr[0]; bl[2 * np][1] = rr[1];
                    bl[2 * np + 1][0] = rr[2]; bl[2 * np + 1][1] = rr[3];
                }
            }
#pragma unroll
            for (int mi = 0; mi < 4; mi++)
#pragma unroll
                for (int ni = 0; ni < 4; ni++) {
                    mma16816(acc[mi][ni], ah[mi], bh[ni]);
                    if (TERMS == 3) {
                        mma16816(acc[mi][ni], ah[mi], bl[ni]);
                        mma16816(acc[mi][ni], al[mi], bh[ni]);
                    }
                }
        }
        __syncthreads();
    }

    // ---------------- epilogue ----------------
#pragma unroll
    for (int mi = 0; mi < 4; mi++) {
#pragma unroll
        for (int half_ = 0; half_ < 2; half_++) {
            const int row = bm * 128 + wm + mi * 16 + g + half_ * 8;
#pragma unroll
            for (int ni = 0; ni < 4; ni++) {
                const int c = bn * 128 + wn + ni * 8 + tig * 2;
                float v0 = acc[mi][ni][half_ * 2 + 0];
                float v1 = acc[mi][ni][half_ * 2 + 1];
                if (EPI == 0) {
                    v0 += bias[c]; v1 += bias[c + 1];
                    *(float2*)&Cf[(size_t)row * N + c] = make_float2(v0, v1);
                } else if (EPI == 2) {
                    v0 += bias[c]; v1 += bias[c + 1];
                    float g0 = 0.5f * v0 * (1.0f + erff(v0 * 0.70710678118654752f));
                    float g1 = 0.5f * v1 * (1.0f + erff(v1 * 0.70710678118654752f));
                    *(__half2*)&Oh[(size_t)row * N + c] = __floats2half2_rn(g0, g1);
                } else if (EPI == 3) {
                    const int h = c >> 7;
                    const int e = c & 127;
                    v0 += bias[h * 192 + e]; v1 += bias[h * 192 + e + 1];
                    const int b_ = row >> 10, s_ = row & 1023;
                    const size_t base = ((size_t)(b_ * Hh + h) * Sq + s_) * DH;
                    if (e < DH) {
                        float s0 = v0 * 8.0f, s1 = v1 * 8.0f;   // sqrt(DH)=8
                        __half h0 = __float2half_rn(s0), h1 = __float2half_rn(s1);
                        *(__half2*)&qh[base + e] = __halves2half2(h0, h1);
                        *(__half2*)&ql[base + e] =
                            __halves2half2(__float2half_rn(s0 - __half2float(h0)),
                                           __float2half_rn(s1 - __half2float(h1)));
                    } else {
                        __half h0 = __float2half_rn(v0), h1 = __float2half_rn(v1);
                        *(__half2*)&kh[base + e - DH] = __halves2half2(h0, h1);
                        *(__half2*)&kl[base + e - DH] =
                            __halves2half2(__float2half_rn(v0 - __half2float(h0)),
                                           __float2half_rn(v1 - __half2float(h1)));
                    }
                } else {   // EPI == 4: V
                    const int h = c >> 6;
                    const int d = c & 63;
                    v0 += bias[h * 192 + 128 + d]; v1 += bias[h * 192 + 128 + d + 1];
                    const int b_ = row >> 10, s_ = row & 1023;
                    const size_t base = ((size_t)(b_ * Hh + h) * Sq + s_) * DH;
                    *(__half2*)&vh[base + d] = __floats2half2_rn(v0, v1);
                }
            }
        }
    }
}

// ---------------- tensor-core flash attention (cp.async + ldmatrix, double-buffered) ----
// Smem stage: Khi | Klo | V, each 64 rows x 64 halves padded to ASROW=72 (144 B rows).
// V kept row-major; PV B-fragments come from ldmatrix.x4.trans.
#define ASROW 72
#define AT_H (64 * ASROW)              // 4608 halves per tile
#define AST_B (3 * AT_H * 2)           // 27648 bytes per stage
#define ATT_SMEM (2 * AST_B + 1024)    // + mask

__global__ __launch_bounds__(256, 2)
void attn_mma(const __half* __restrict__ qg, const __half* __restrict__ qlg,
              const __half* __restrict__ kg, const __half* __restrict__ klg,
              const __half* __restrict__ vg, const unsigned char* __restrict__ maskg,
              __half* __restrict__ ctx) {
    extern __shared__ char asmem[];
    const uint32_t sbase = smem_u32(asmem);
    unsigned char* Msall = (unsigned char*)(asmem + 2 * AST_B);

    const int tid = threadIdx.x;
    const int w = tid >> 5, lane = tid & 31;
    const int g = lane >> 2, tig = lane & 3;
    const int quad = lane >> 3, lr = lane & 7;
    const int qblk = blockIdx.x, h = blockIdx.y, b = blockIdx.z;
    const size_t bh = (size_t)(b * Hh + h) * Sq;
    const int qrow0 = qblk * 128 + w * 16;

    // ldmatrix per-lane offsets (bytes)
    const uint32_t boff = (((quad >> 1) * 8 + lr) * ASROW + (quad & 1) * 8) * 2;   // K (non-trans)
    const uint32_t voff = (((quad & 1) * 8 + lr) * ASROW) * 2 + (quad >> 1) * 16;  // V (trans)

    // mask for this batch, loaded once
    *(uchar4*)&Msall[tid * 4] = ((const uchar4*)(maskg + (size_t)b * Sq))[tid];

    // Q fragments (hi/lo) in registers for the whole kernel
    uint32_t qfh[4][4], qfl[4][4];
#pragma unroll
    for (int ks = 0; ks < 4; ks++) {
        const int k0 = ks * 16 + tig * 2;
        const size_t r0 = (bh + qrow0 + g) * DH;
        const size_t r1 = (bh + qrow0 + g + 8) * DH;
        qfh[ks][0] = *(const uint32_t*)(qg + r0 + k0);
        qfh[ks][1] = *(const uint32_t*)(qg + r1 + k0);
        qfh[ks][2] = *(const uint32_t*)(qg + r0 + k0 + 8);
        qfh[ks][3] = *(const uint32_t*)(qg + r1 + k0 + 8);
        qfl[ks][0] = *(const uint32_t*)(qlg + r0 + k0);
        qfl[ks][1] = *(const uint32_t*)(qlg + r1 + k0);
        qfl[ks][2] = *(const uint32_t*)(qlg + r0 + k0 + 8);
        qfl[ks][3] = *(const uint32_t*)(qlg + r1 + k0 + 8);
    }

    // cp.async stage fill: 3 tiles x 512 x 16B chunks; 6 chunks per thread
    auto issue_stage = [&](int kt) {
        const uint32_t dst0 = sbase + (kt & 1) * AST_B;
#pragma unroll
        for (int i = 0; i < 6; i++) {
            const int c = tid + i * 256;       // 0..1535
            const int t = c >> 9;              // tile: 0=Khi 1=Klo 2=V
            const int cc = c & 511;
            const int row = cc >> 3, col = cc & 7;
            const __half* src = (t == 0 ? kg : (t == 1 ? klg : vg))
                                + (bh + kt * 64 + row) * DH + col * 8;
            CP_ASYNC16(dst0 + t * (AT_H * 2) + row * (ASROW * 2) + col * 16, src);
        }
        CP_COMMIT();
    };

    float out[8][4];
#pragma unroll
    for (int nt = 0; nt < 8; nt++)
#pragma unroll
        for (int e = 0; e < 4; e++) out[nt][e] = 0.f;
    float m0 = -1e30f, m1 = -1e30f, l0 = 0.f, l1 = 0.f;

    issue_stage(0);

    for (int kt = 0; kt < 16; kt++) {
        if (kt + 1 < 16) { issue_stage(kt + 1); CP_WAIT1(); } else { CP_WAIT0(); }
        __syncthreads();

        const uint32_t sK  = sbase + (kt & 1) * AST_B;
        const uint32_t sKl = sK + AT_H * 2;
        const uint32_t sV  = sK + 2 * AT_H * 2;

        // ---- S = Q K^T (3-term) via ldmatrix ----
        float s[8][4];
#pragma unroll
        for (int nt = 0; nt < 8; nt++)
#pragma unroll
            for (int e = 0; e < 4; e++) s[nt][e] = 0.f;
#pragma unroll
        for (int ks = 0; ks < 4; ks++) {
            const uint32_t k0b = (uint32_t)(ks * 16) * 2;
#pragma unroll
            for (int np = 0; np < 4; np++) {
                const uint32_t rbase = (uint32_t)(np * 16 * ASROW) * 2 + k0b;
                uint32_t rh[4], rl[4];
                ldsm4(rh, sK + rbase + boff);
                ldsm4(rl, sKl + rbase + boff);
                mma16816(s[2 * np],     qfh[ks], rh);
                mma16816(s[2 * np],     qfl[ks], rh);
                mma16816(s[2 * np],     qfh[ks], rl);
                mma16816(s[2 * np + 1], qfh[ks], rh + 2);
                mma16816(s[2 * np + 1], qfl[ks], rh + 2);
                mma16816(s[2 * np + 1], qfh[ks], rl + 2);
            }
        }

        // ---- mask + online softmax ----
        const unsigned char* Mt = Msall + kt * 64;
        float mx0 = -1e30f, mx1 = -1e30f;
#pragma unroll
        for (int nt = 0; nt < 8; nt++) {
            const int col = nt * 8 + tig * 2;
            if (Mt[col])     { s[nt][0] = -1e30f; s[nt][2] = -1e30f; }
            if (Mt[col + 1]) { s[nt][1] = -1e30f; s[nt][3] = -1e30f; }
            mx0 = fmaxf(mx0, fmaxf(s[nt][0], s[nt][1]));
            mx1 = fmaxf(mx1, fmaxf(s[nt][2], s[nt][3]));
        }
        mx0 = fmaxf(mx0, __shfl_xor_sync(0xffffffffu, mx0, 1));
        mx0 = fmaxf(mx0, __shfl_xor_sync(0xffffffffu, mx0, 2));
        mx1 = fmaxf(mx1, __shfl_xor_sync(0xffffffffu, mx1, 1));
        mx1 = fmaxf(mx1, __shfl_xor_sync(0xffffffffu, mx1, 2));
        const float mn0 = fmaxf(m0, mx0), mn1 = fmaxf(m1, mx1);
        const float sc0 = __expf(m0 - mn0), sc1 = __expf(m1 - mn1);
        m0 = mn0; m1 = mn1;
        float rs0 = 0.f, rs1 = 0.f;
#pragma unroll
        for (int nt = 0; nt < 8; nt++) {
            s[nt][0] = __expf(s[nt][0] - mn0);
            s[nt][1] = __expf(s[nt][1] - mn0);
            s[nt][2] = __expf(s[nt][2] - mn1);
            s[nt][3] = __expf(s[nt][3] - mn1);
            rs0 += s[nt][0] + s[nt][1];
            rs1 += s[nt][2] + s[nt][3];
            out[nt][0] *= sc0; out[nt][1] *= sc0;
            out[nt][2] *= sc1; out[nt][3] *= sc1;
        }
        rs0 += __shfl_xor_sync(0xffffffffu, rs0, 1);
        rs0 += __shfl_xor_sync(0xffffffffu, rs0, 2);
        rs1 += __shfl_xor_sync(0xffffffffu, rs1, 1);
        rs1 += __shfl_xor_sync(0xffffffffu, rs1, 2);
        l0 = l0 * sc0 + rs0;
        l1 = l1 * sc1 + rs1;

        // ---- out += P V via ldmatrix.trans (V row-major) ----
#pragma unroll
        for (int kg2 = 0; kg2 < 4; kg2++) {
            uint32_t pa[4];
            pa[0] = packh2(s[2 * kg2][0], s[2 * kg2][1]);
            pa[1] = packh2(s[2 * kg2][2], s[2 * kg2][3]);
            pa[2] = packh2(s[2 * kg2 + 1][0], s[2 * kg2 + 1][1]);
            pa[3] = packh2(s[2 * kg2 + 1][2], s[2 * kg2 + 1][3]);
            const uint32_t kbase = (uint32_t)(kg2 * 16 * ASROW) * 2;
#pragma unroll
            for (int ng = 0; ng < 4; ng++) {
                uint32_t rr[4];
                ldsm4t(rr, sV + kbase + (uint32_t)(ng * 32) + voff);
                mma16816(out[2 * ng],     pa, rr);
                mma16816(out[2 * ng + 1], pa, rr + 2);
            }
        }
        __syncthreads();
    }

    const float i0 = 1.0f / l0, i1 = 1.0f / l1;
    const int r0 = qrow0 + g, r1 = qrow0 + g + 8;
    __half* p0 = ctx + ((size_t)(b * Sq + r0) * Hh + h) * DH;
    __half* p1 = ctx + ((size_t)(b * Sq + r1) * Hh + h) * DH;
#pragma unroll
    for (int nt = 0; nt < 8; nt++) {
        const int dh = nt * 8 + tig * 2;
        *(__half2*)(p0 + dh) = __floats2half2_rn(out[nt][0] * i0, out[nt][1] * i0);
        *(__half2*)(p1 + dh) = __floats2half2_rn(out[nt][2] * i1, out[nt][3] * i1);
    }
}

// ---------------- fused add + LayerNorm (+ optional fp16 out) ----------------
__global__ __launch_bounds__(256)
void addln_kernel(const float* __restrict__ a, const float* __restrict__ b,
                  const float* __restrict__ g, const float* __restrict__ bt,
                  float* __restrict__ o, __half* __restrict__ oh) {
    __shared__ float redS[8], redQ[8], outMV[2];
    const int row = blockIdx.x;
    const int t = threadIdx.x;
    const float* ar = a + (size_t)row * Dm;
    const float* br = b + (size_t)row * Dm;

    float v[4];
    float s = 0.f, sq = 0.f;
#pragma unroll
    for (int i = 0; i < 4; i++) {
        int idx = t + i * 256;
        float x = ar[idx] + br[idx];
        v[i] = x;
        s += x;
        sq = fmaf(x, x, sq);
    }
#pragma unroll
    for (int off = 16; off; off >>= 1) {
        s += __shfl_xor_sync(0xFFFFFFFFu, s, off);
        sq += __shfl_xor_sync(0xFFFFFFFFu, sq, off);
    }
    if ((t & 31) == 0) { redS[t >> 5] = s; redQ[t >> 5] = sq; }
    __syncthreads();
    if (t < 32) {
        float s2 = (t < 8) ? redS[t] : 0.f;
        float q2 = (t < 8) ? redQ[t] : 0.f;
#pragma unroll
        for (int off = 4; off; off >>= 1) {
            s2 += __shfl_xor_sync(0xFFFFFFFFu, s2, off);
            q2 += __shfl_xor_sync(0xFFFFFFFFu, q2, off);
        }
        if (t == 0) {
            float mean = s2 * (1.0f / Dm);
            float var = q2 * (1.0f / Dm) - mean * mean;
            outMV[0] = mean;
            outMV[1] = rsqrtf(var + 1e-5f);
        }
    }
    __syncthreads();
    const float mean = outMV[0], rstd = outMV[1];
    float* orow = o + (size_t)row * Dm;
#pragma unroll
    for (int i = 0; i < 4; i++) {
        int idx = t + i * 256;
        float y = (v[i] - mean) * rstd * g[idx] + bt[idx];
        orow[idx] = y;
        if (oh) oh[(size_t)row * Dm + idx] = __float2half_rn(y);
    }
}

// ---------------- launch ----------------
extern "C" void kernel_launch(void* const* d_in, const int* in_sizes, int n_in,
                              void* d_out, int out_size) {
    const float* seq  = (const float*)d_in[0];
    const unsigned char* mask = (const unsigned char*)d_in[1];
    const float* Wqkv = (const float*)d_in[2];
    const float* bqkv = (const float*)d_in[3];
    const float* Wo   = (const float*)d_in[4];
    const float* bo   = (const float*)d_in[5];
    const float* g1   = (const float*)d_in[6];
    const float* b1   = (const float*)d_in[7];
    const float* Wi   = (const float*)d_in[8];
    const float* bi   = (const float*)d_in[9];
    const float* Wout = (const float*)d_in[10];
    const float* bout = (const float*)d_in[11];
    const float* g2   = (const float*)d_in[12];
    const float* b2   = (const float*)d_in[13];
    float* out = (float*)d_out;

    __half *seqh, *seql, *Bqkh, *Bqkl, *Bvh, *Woh, *Wih, *Wouth;
    __half *qh, *ql, *kh, *kl, *vh, *ctxh, *xh, *hh;
    float *attn, *x, *y;
    cudaGetSymbolAddress((void**)&seqh, g_seqh);   cudaGetSymbolAddress((void**)&seql, g_seql);
    cudaGetSymbolAddress((void**)&Bqkh, g_Bqkh);   cudaGetSymbolAddress((void**)&Bqkl, g_Bqkl);
    cudaGetSymbolAddress((void**)&Bvh, g_Bvh);
    cudaGetSymbolAddress((void**)&Woh, g_Woh);
    cudaGetSymbolAddress((void**)&Wih, g_Wih);
    cudaGetSymbolAddress((void**)&Wouth, g_Wouth);
    cudaGetSymbolAddress((void**)&qh, g_qh);       cudaGetSymbolAddress((void**)&ql, g_ql);
    cudaGetSymbolAddress((void**)&kh, g_kh);       cudaGetSymbolAddress((void**)&kl, g_kl);
    cudaGetSymbolAddress((void**)&vh, g_vh);       cudaGetSymbolAddress((void**)&ctxh, g_ctxh);
    cudaGetSymbolAddress((void**)&xh, g_xh);       cudaGetSymbolAddress((void**)&hh, g_hh);
    cudaGetSymbolAddress((void**)&attn, g_attn);   cudaGetSymbolAddress((void**)&x, g_x);
    cudaGetSymbolAddress((void**)&y, g_y);

    const int SM3 = 2 * 4 * TILE_B;   // 147456
    const int SM1 = 2 * 2 * TILE_B;   // 73728
    cudaFuncSetAttribute(mma_gemm<3, 3, 1>, cudaFuncAttributeMaxDynamicSharedMemorySize, SM3);
    cudaFuncSetAttribute(mma_gemm<4, 1, 2>, cudaFuncAttributeMaxDynamicSharedMemorySize, SM1);
    cudaFuncSetAttribute(mma_gemm<0, 1, 2>, cudaFuncAttributeMaxDynamicSharedMemorySize, SM1);
    cudaFuncSetAttribute(mma_gemm<2, 1, 2>, cudaFuncAttributeMaxDynamicSharedMemorySize, SM1);
    cudaFuncSetAttribute(attn_mma, cudaFuncAttributeMaxDynamicSharedMemorySize, ATT_SMEM);

    // weight packing:
    // QK columns [0,128) per head -> Bqk (2048 rows, hi/lo); V columns [128,192) -> Bv
    packW_kernel<<<dim3(4, 32, Hh), dim3(32, 8)>>>(Wqkv, Bqkh, Bqkl, Dm, 192, 0, 128);
    packW_kernel<<<dim3(2, 32, Hh), dim3(32, 8)>>>(Wqkv, Bvh, nullptr, Dm, 192, 128, 64);
    packW_kernel<<<dim3(Dm / 32, Dm / 32, 1), dim3(32, 8)>>>(Wo, Woh, nullptr, Dm, Dm, 0, Dm);
    packW_kernel<<<dim3(Ii / 32, Dm / 32, 1), dim3(32, 8)>>>(Wi, Wih, nullptr, Dm, Ii, 0, Ii);
    packW_kernel<<<dim3(Dm / 32, Ii / 32, 1), dim3(32, 8)>>>(Wout, Wouth, nullptr, Ii, Dm, 0, Dm);

    // seq -> fp16 hi/lo
    split_kernel<<<(ROWS * Dm / 4 + 255) / 256, 256>>>(seq, seqh, seql, ROWS * Dm);

    // QK projection (3-term) -> q(hi/lo)*8, k(hi/lo)
    mma_gemm<3, 3, 1><<<dim3(2048 / 128, ROWS / 128), 256, SM3>>>(
        seqh, seql, Bqkh, Bqkl, bqkv, nullptr, qh, ql, kh, kl, nullptr, nullptr, Dm, 2048);

    // V projection (1-term) -> v fp16
    mma_gemm<4, 1, 2><<<dim3(1024 / 128, ROWS / 128), 256, SM1>>>(
        seqh, nullptr, Bvh, nullptr, bqkv, nullptr,
        nullptr, nullptr, nullptr, nullptr, vh, nullptr, Dm, 1024);

    // tensor-core flash attention -> ctx fp16
    attn_mma<<<dim3(8, Hh, Bz), 256, ATT_SMEM>>>(qh, ql, kh, kl, vh, mask, ctxh);

    // output projection (1-term)
    mma_gemm<0, 1, 2><<<dim3(Dm / 128, ROWS / 128), 256, SM1>>>(
        ctxh, nullptr, Woh, nullptr, bo, attn,
        nullptr, nullptr, nullptr, nullptr, nullptr, nullptr, Dm, Dm);

    // x = LN(seq + attn) (+ fp16 for Wi)
    addln_kernel<<<ROWS, 256>>>(seq, attn, g1, b1, x, xh);

    // h = gelu(x @ Wi + bi) (1-term) -> fp16
    mma_gemm<2, 1, 2><<<dim3(Ii / 128, ROWS / 128), 256, SM1>>>(
        xh, nullptr, Wih, nullptr, bi, nullptr,
        nullptr, nullptr, nullptr, nullptr, nullptr, hh, Dm, Ii);

    // y = h @ Wout + bout (1-term)
    mma_gemm<0, 1, 2><<<dim3(Dm / 128, ROWS / 128), 256, SM1>>>(
        hh, nullptr, Wouth, nullptr, bout, y,
        nullptr, nullptr, nullptr, nullptr, nullptr, nullptr, Ii, Dm);

    // out = LN(x + y)
    addln_kernel<<<ROWS, 256>>>(x, y, g2, b2, out, nullptr);
}

// round 11
// speedup vs baseline: 5.3851x; 1.0001x over previous
#include <cuda_runtime.h>
#include <cuda_fp16.h>
#include <math.h>
#include <stdint.h>

#define Bz 8
#define Sq 1024
#define Dm 1024
#define Hh 16
#define DH 64
#define Ii 4096
#define ROWS (Bz * Sq)

// ---------------- scratch (static device memory; no allocations) ----------------
__device__ __half g_seqh[ROWS * Dm], g_seql[ROWS * Dm];
__device__ __half g_Bqkh[2048 * Dm], g_Bqkl[2048 * Dm];
__device__ __half g_Bvh[1024 * Dm];
__device__ __half g_Woh[Dm * Dm];
__device__ __half g_Wih[Ii * Dm];
__device__ __half g_Wouth[Dm * Ii];
__device__ __half g_qh[ROWS * Dm], g_ql[ROWS * Dm];
__device__ __half g_kh[ROWS * Dm], g_kl[ROWS * Dm];
__device__ __half g_vh[ROWS * Dm];
__device__ __half g_ctxh[ROWS * Dm];
__device__ __half g_attnh[ROWS * Dm];
__device__ float g_x[ROWS * Dm];
__device__ __half g_xh[ROWS * Dm];
__device__ __half g_hh[ROWS * Ii];
__device__ __half g_yh[ROWS * Dm];

// ---------------- helpers ----------------
__device__ __forceinline__ uint32_t smem_u32(const void* p) {
    uint32_t r;
    asm("{ .reg .u64 t; cvta.to.shared.u64 t, %1; cvt.u32.u64 %0, t; }" : "=r"(r) : "l"(p));
    return r;
}
#define CP_ASYNC16(dst, src) \
    asm volatile("cp.async.cg.shared.global [%0], [%1], 16;" :: "r"(dst), "l"(src) : "memory")
#define CP_COMMIT() asm volatile("cp.async.commit_group;" ::: "memory")
#define CP_WAIT2()  asm volatile("cp.async.wait_group 2;" ::: "memory")
#define CP_WAIT1()  asm volatile("cp.async.wait_group 1;" ::: "memory")
#define CP_WAIT0()  asm volatile("cp.async.wait_group 0;" ::: "memory")

__device__ __forceinline__ void mma16816(float* d, const uint32_t* a, const uint32_t* b) {
    asm volatile(
        "mma.sync.aligned.m16n8k16.row.col.f32.f16.f16.f32 "
        "{%0,%1,%2,%3}, {%4,%5,%6,%7}, {%8,%9}, {%0,%1,%2,%3};"
        : "+f"(d[0]), "+f"(d[1]), "+f"(d[2]), "+f"(d[3])
        : "r"(a[0]), "r"(a[1]), "r"(a[2]), "r"(a[3]), "r"(b[0]), "r"(b[1]));
}
__device__ __forceinline__ void ldsm4(uint32_t* r, uint32_t a) {
    asm volatile("ldmatrix.sync.aligned.m8n8.x4.shared.b16 {%0,%1,%2,%3}, [%4];"
                 : "=r"(r[0]), "=r"(r[1]), "=r"(r[2]), "=r"(r[3]) : "r"(a));
}
__device__ __forceinline__ void ldsm4t(uint32_t* r, uint32_t a) {
    asm volatile("ldmatrix.sync.aligned.m8n8.x4.trans.shared.b16 {%0,%1,%2,%3}, [%4];"
                 : "=r"(r[0]), "=r"(r[1]), "=r"(r[2]), "=r"(r[3]) : "r"(a));
}
__device__ __forceinline__ uint32_t packh2(float a, float b) {
    __half2 h = __floats2half2_rn(a, b);
    return *(uint32_t*)&h;
}

// ---------------- weight pack: per-head column window, transpose + fp16 (hi[/lo]) ----
__global__ void packW_kernel(const float* __restrict__ w, __half* __restrict__ oh,
                             __half* __restrict__ ol, int K, int N, int ncol0, int nout) {
    __shared__ float t[32][33];
    const int z = blockIdx.z;
    const float* in = w + (size_t)z * K * N;
    __half* poh = oh + (size_t)z * nout * K;
    __half* pol = ol ? ol + (size_t)z * nout * K : nullptr;
    const int n0 = blockIdx.x * 32, k0 = blockIdx.y * 32;
    const int tx = threadIdx.x, ty = threadIdx.y;
#pragma unroll
    for (int i = 0; i < 32; i += 8)
        t[ty + i][tx] = in[(size_t)(k0 + ty + i) * N + ncol0 + n0 + tx];
    __syncthreads();
#pragma unroll
    for (int i = 0; i < 32; i += 8) {
        float v = t[tx][ty + i];
        __half hi = __float2half_rn(v);
        size_t o = (size_t)(n0 + ty + i) * K + k0 + tx;
        poh[o] = hi;
        if (pol) pol[o] = __float2half_rn(v - __half2float(hi));
    }
}

// ---------------- fp32 -> fp16 hi/lo ----------------
__global__ void split_kernel(const float* __restrict__ in, __half* __restrict__ oh,
                             __half* __restrict__ ol, int n) {
    int i = (blockIdx.x * 256 + threadIdx.x) * 4;
    if (i < n) {
        float4 v = *(const float4*)(in + i);
        __half h0 = __float2half_rn(v.x), h1 = __float2half_rn(v.y);
        __half h2 = __float2half_rn(v.z), h3 = __float2half_rn(v.w);
        __half2* ph = (__half2*)(oh + i);
        ph[0] = __halves2half2(h0, h1);
        ph[1] = __halves2half2(h2, h3);
        __half2* pl = (__half2*)(ol + i);
        pl[0] = __halves2half2(__float2half_rn(v.x - __half2float(h0)),
                               __float2half_rn(v.y - __half2float(h1)));
        pl[1] = __halves2half2(__float2half_rn(v.z - __half2float(h2)),
                               __float2half_rn(v.w - __half2float(h3)));
    }
}

// ---------------- mma.sync GEMM (ldmatrix fragments) ----------------
// TERMS=3: acc = Ah*Bh + Ah*Bl + Al*Bh (3-stage pipeline, occ 1)
// TERMS=1: acc = A*B                   (2-stage pipeline, occ 2)
// EPI 2: Oh = fp16(gelu(v + bias[c]))
// EPI 3: QK scatter (N=2048): c -> h=c>>7, e=c&127; e<64: q*8 hi/lo, else k hi/lo
// EPI 4: V write   (N=1024): c -> h=c>>6, d=c&63 -> vh fp16
// EPI 5: Oh = fp16(v + bias[c])
#define SROW 72
#define TILE_H (128 * SROW)
#define TILE_B (TILE_H * 2)            // 18432 bytes

template <int EPI, int TERMS, int OCC>
__global__ __launch_bounds__(256, OCC)
void mma_gemm(const __half* __restrict__ Ah, const __half* __restrict__ Al,
              const __half* __restrict__ Bh, const __half* __restrict__ Bl,
              const float* __restrict__ bias, float* __restrict__ Cf,
              __half* __restrict__ qh, __half* __restrict__ ql,
              __half* __restrict__ kh, __half* __restrict__ kl,
              __half* __restrict__ vh, __half* __restrict__ Oh,
              int K, int N) {
    constexpr int NTILES = (TERMS == 3) ? 4 : 2;
    constexpr int STAGES = (TERMS == 3) ? 3 : 2;
    constexpr int STAGE_B = NTILES * TILE_B;
    extern __shared__ char smem[];
    const uint32_t sb = smem_u32(smem);
    const int tid = threadIdx.x;
    const int w = tid >> 5, lane = tid & 31;
    const int g = lane >> 2, tig = lane & 3;
    const int quad = lane >> 3, lr = lane & 7;
    const int bm = blockIdx.y, bn = blockIdx.x;
    const int wm = (w >> 2) * 64;
    const int wn = (w & 3) * 32;

    const uint32_t aoff = (((quad & 1) * 8 + lr) * SROW + (quad >> 1) * 8) * 2;
    const uint32_t boff = (((quad >> 1) * 8 + lr) * SROW + (quad & 1) * 8) * 2;

    const __half* gp[4];
    gp[0] = Ah + (size_t)bm * 128 * K;
    if (TERMS == 3) {
        gp[1] = Al + (size_t)bm * 128 * K;
        gp[2] = Bh + (size_t)bn * 128 * K;
        gp[3] = Bl + (size_t)bn * 128 * K;
    } else {
        gp[1] = Bh + (size_t)bn * 128 * K;
    }

    int lrow[4], lcb[4];
#pragma unroll
    for (int i = 0; i < 4; i++) { int c = tid + i * 256; lrow[i] = c >> 3; lcb[i] = c & 7; }

    float acc[4][4][4];
#pragma unroll
    for (int mi = 0; mi < 4; mi++)
#pragma unroll
        for (int ni = 0; ni < 4; ni++)
#pragma unroll
            for (int e = 0; e < 4; e++) acc[mi][ni][e] = 0.f;

    const int NT = K / 64;

    auto issue_stage = [&](int kt) {
        const uint32_t dstS = sb + (kt % STAGES) * STAGE_B;
#pragma unroll
        for (int t = 0; t < NTILES; t++) {
            const __half* src = gp[t] + kt * 64;
#pragma unroll
            for (int i = 0; i < 4; i++) {
                CP_ASYNC16(dstS + t * TILE_B + lrow[i] * (SROW * 2) + lcb[i] * 16,
                           src + (size_t)lrow[i] * K + lcb[i] * 8);
            }
        }
        CP_COMMIT();
    };

    issue_stage(0);
    if (STAGES == 3 && NT > 1) issue_stage(1);

    for (int kt = 0; kt < NT; kt++) {
        if (STAGES == 3) {
            if (kt + 2 < NT) { issue_stage(kt + 2); CP_WAIT2(); }
            else if (kt + 1 < NT) { CP_WAIT1(); }
            else { CP_WAIT0(); }
        } else {
            if (kt + 1 < NT) { issue_stage(kt + 1); CP_WAIT1(); } else { CP_WAIT0(); }
        }
        __syncthreads();

        const uint32_t sA  = sb + (kt % STAGES) * STAGE_B;
        const uint32_t sAl = sA + TILE_B;
        const uint32_t sBh = sA + ((TERMS == 3) ? 2 : 1) * TILE_B;
        const uint32_t sBl = sA + 3 * TILE_B;

#pragma unroll
        for (int ks = 0; ks < 4; ks++) {
            const uint32_t k0b = (uint32_t)(ks * 16) * 2;
            uint32_t ah[4][4], al[4][4], bh[4][2], bl[4][2];
#pragma unroll
            for (int mi = 0; mi < 4; mi++) {
                const uint32_t rbase = (uint32_t)((wm + mi * 16) * SROW) * 2 + k0b;
                ldsm4(ah[mi], sA + rbase + aoff);
                if (TERMS == 3) ldsm4(al[mi], sAl + rbase + aoff);
            }
#pragma unroll
            for (int np = 0; np < 2; np++) {
                const uint32_t rbase = (uint32_t)((wn + np * 16) * SROW) * 2 + k0b;
                uint32_t rr[4];
                ldsm4(rr, sBh + rbase + boff);
                bh[2 * np][0] = rr[0]; bh[2 * np][1] = rr[1];
                bh[2 * np + 1][0] = rr[2]; bh[2 * np + 1][1] = rr[3];
                if (TERMS == 3) {
                    ldsm4(rr, sBl + rbase + boff);
                    bl[2 * np][0] = rr[0]; bl[2 * np][1] = rr[1];
                    bl[2 * np + 1][0] = rr[2]; bl[2 * np + 1][1] = rr[3];
                }
            }
#pragma unroll
            for (int mi = 0; mi < 4; mi++)
#pragma unroll
                for (int ni = 0; ni < 4; ni++) {
                    mma16816(acc[mi][ni], ah[mi], bh[ni]);
                    if (TERMS == 3) {
                        mma16816(acc[mi][ni], ah[mi], bl[ni]);
                        mma16816(acc[mi][ni], al[mi], bh[ni]);
                    }
                }
        }
        __syncthreads();
    }

    // ---------------- epilogue ----------------
#pragma unroll
    for (int mi = 0; mi < 4; mi++) {
#pragma unroll
        for (int half_ = 0; half_ < 2; half_++) {
            const int row = bm * 128 + wm + mi * 16 + g + half_ * 8;
#pragma unroll
            for (int ni = 0; ni < 4; ni++) {
                const int c = bn * 128 + wn + ni * 8 + tig * 2;
                float v0 = acc[mi][ni][half_ * 2 + 0];
                float v1 = acc[mi][ni][half_ * 2 + 1];
                if (EPI == 5) {
                    v0 += bias[c]; v1 += bias[c + 1];
                    *(__half2*)&Oh[(size_t)row * N + c] = __floats2half2_rn(v0, v1);
                } else if (EPI == 2) {
                    v0 += bias[c]; v1 += bias[c + 1];
                    float g0 = 0.5f * v0 * (1.0f + erff(v0 * 0.70710678118654752f));
                    float g1 = 0.5f * v1 * (1.0f + erff(v1 * 0.70710678118654752f));
                    *(__half2*)&Oh[(size_t)row * N + c] = __floats2half2_rn(g0, g1);
                } else if (EPI == 3) {
                    const int h = c >> 7;
                    const int e = c & 127;
                    v0 += bias[h * 192 + e]; v1 += bias[h * 192 + e + 1];
                    const int b_ = row >> 10, s_ = row & 1023;
                    const size_t base = ((size_t)(b_ * Hh + h) * Sq + s_) * DH;
                    if (e < DH) {
                        float s0 = v0 * 8.0f, s1 = v1 * 8.0f;   // sqrt(DH)=8
                        __half h0 = __float2half_rn(s0), h1 = __float2half_rn(s1);
                        *(__half2*)&qh[base + e] = __halves2half2(h0, h1);
                        *(__half2*)&ql[base + e] =
                            __halves2half2(__float2half_rn(s0 - __half2float(h0)),
                                           __float2half_rn(s1 - __half2float(h1)));
                    } else {
                        __half h0 = __float2half_rn(v0), h1 = __float2half_rn(v1);
                        *(__half2*)&kh[base + e - DH] = __halves2half2(h0, h1);
                        *(__half2*)&kl[base + e - DH] =
                            __halves2half2(__float2half_rn(v0 - __half2float(h0)),
                                           __float2half_rn(v1 - __half2float(h1)));
                    }
                } else {   // EPI == 4: V
                    const int h = c >> 6;
                    const int d = c & 63;
                    v0 += bias[h * 192 + 128 + d]; v1 += bias[h * 192 + 128 + d + 1];
                    const int b_ = row >> 10, s_ = row & 1023;
                    const size_t base = ((size_t)(b_ * Hh + h) * Sq + s_) * DH;
                    *(__half2*)&vh[base + d] = __floats2half2_rn(v0, v1);
                }
            }
        }
    }
}

// ---------------- tensor-core flash attention (cp.async + ldmatrix, double-buffered) ----
#define ASROW 72
#define AT_H (64 * ASROW)              // 4608 halves per tile
#define AST_B (3 * AT_H * 2)           // 27648 bytes per stage
#define ATT_SMEM (2 * AST_B + 1024)    // + mask

__global__ __launch_bounds__(256, 2)
void attn_mma(const __half* __restrict__ qg, const __half* __restrict__ qlg,
              const __half* __restrict__ kg, const __half* __restrict__ klg,
              const __half* __restrict__ vg, const unsigned char* __restrict__ maskg,
              __half* __restrict__ ctx) {
    extern __shared__ char asmem[];
    const uint32_t sbase = smem_u32(asmem);
    unsigned char* Msall = (unsigned char*)(asmem + 2 * AST_B);

    const int tid = threadIdx.x;
    const int w = tid >> 5, lane = tid & 31;
    const int g = lane >> 2, tig = lane & 3;
    const int quad = lane >> 3, lr = lane & 7;
    const int qblk = blockIdx.x, h = blockIdx.y, b = blockIdx.z;
    const size_t bh = (size_t)(b * Hh + h) * Sq;
    const int qrow0 = qblk * 128 + w * 16;

    const uint32_t boff = (((quad >> 1) * 8 + lr) * ASROW + (quad & 1) * 8) * 2;
    const uint32_t voff = (((quad & 1) * 8 + lr) * ASROW) * 2 + (quad >> 1) * 16;

    *(uchar4*)&Msall[tid * 4] = ((const uchar4*)(maskg + (size_t)b * Sq))[tid];

    uint32_t qfh[4][4], qfl[4][4];
#pragma unroll
    for (int ks = 0; ks < 4; ks++) {
        const int k0 = ks * 16 + tig * 2;
        const size_t r0 = (bh + qrow0 + g) * DH;
        const size_t r1 = (bh + qrow0 + g + 8) * DH;
        qfh[ks][0] = *(const uint32_t*)(qg + r0 + k0);
        qfh[ks][1] = *(const uint32_t*)(qg + r1 + k0);
        qfh[ks][2] = *(const uint32_t*)(qg + r0 + k0 + 8);
        qfh[ks][3] = *(const uint32_t*)(qg + r1 + k0 + 8);
        qfl[ks][0] = *(const uint32_t*)(qlg + r0 + k0);
        qfl[ks][1] = *(const uint32_t*)(qlg + r1 + k0);
        qfl[ks][2] = *(const uint32_t*)(qlg + r0 + k0 + 8);
        qfl[ks][3] = *(const uint32_t*)(qlg + r1 + k0 + 8);
    }

    auto issue_stage = [&](int kt) {
        const uint32_t dst0 = sbase + (kt & 1) * AST_B;
#pragma unroll
        for (int i = 0; i < 6; i++) {
            const int c = tid + i * 256;
            const int t = c >> 9;
            const int cc = c & 511;
            const int row = cc >> 3, col = cc & 7;
            const __half* src = (t == 0 ? kg : (t == 1 ? klg : vg))
                                + (bh + kt * 64 + row) * DH + col * 8;
            CP_ASYNC16(dst0 + t * (AT_H * 2) + row * (ASROW * 2) + col * 16, src);
        }
        CP_COMMIT();
    };

    float out[8][4];
#pragma unroll
    for (int nt = 0; nt < 8; nt++)
#pragma unroll
        for (int e = 0; e < 4; e++) out[nt][e] = 0.f;
    float m0 = -1e30f, m1 = -1e30f, l0 = 0.f, l1 = 0.f;

    issue_stage(0);

    for (int kt = 0; kt < 16; kt++) {
        if (kt + 1 < 16) { issue_stage(kt + 1); CP_WAIT1(); } else { CP_WAIT0(); }
        __syncthreads();

        const uint32_t sK  = sbase + (kt & 1) * AST_B;
        const uint32_t sKl = sK + AT_H * 2;
        const uint32_t sV  = sK + 2 * AT_H * 2;

        float s[8][4];
#pragma unroll
        for (int nt = 0; nt < 8; nt++)
#pragma unroll
            for (int e = 0; e < 4; e++) s[nt][e] = 0.f;
#pragma unroll
        for (int ks = 0; ks < 4; ks++) {
            const uint32_t k0b = (uint32_t)(ks * 16) * 2;
#pragma unroll
            for (int np = 0; np < 4; np++) {
                const uint32_t rbase = (uint32_t)(np * 16 * ASROW) * 2 + k0b;
                uint32_t rh[4], rl[4];
                ldsm4(rh, sK + rbase + boff);
                ldsm4(rl, sKl + rbase + boff);
                mma16816(s[2 * np],     qfh[ks], rh);
                mma16816(s[2 * np],     qfl[ks], rh);
                mma16816(s[2 * np],     qfh[ks], rl);
                mma16816(s[2 * np + 1], qfh[ks], rh + 2);
                mma16816(s[2 * np + 1], qfl[ks], rh + 2);
                mma16816(s[2 * np + 1], qfh[ks], rl + 2);
            }
        }

        const unsigned char* Mt = Msall + kt * 64;
        float mx0 = -1e30f, mx1 = -1e30f;
#pragma unroll
        for (int nt = 0; nt < 8; nt++) {
            const int col = nt * 8 + tig * 2;
            if (Mt[col])     { s[nt][0] = -1e30f; s[nt][2] = -1e30f; }
            if (Mt[col + 1]) { s[nt][1] = -1e30f; s[nt][3] = -1e30f; }
            mx0 = fmaxf(mx0, fmaxf(s[nt][0], s[nt][1]));
            mx1 = fmaxf(mx1, fmaxf(s[nt][2], s[nt][3]));
        }
        mx0 = fmaxf(mx0, __shfl_xor_sync(0xffffffffu, mx0, 1));
        mx0 = fmaxf(mx0, __shfl_xor_sync(0xffffffffu, mx0, 2));
        mx1 = fmaxf(mx1, __shfl_xor_sync(0xffffffffu, mx1, 1));
        mx1 = fmaxf(mx1, __shfl_xor_sync(0xffffffffu, mx1, 2));
        const float mn0 = fmaxf(m0, mx0), mn1 = fmaxf(m1, mx1);
        const float sc0 = __expf(m0 - mn0), sc1 = __expf(m1 - mn1);
        m0 = mn0; m1 = mn1;
        float rs0 = 0.f, rs1 = 0.f;
#pragma unroll
        for (int nt = 0; nt < 8; nt++) {
            s[nt][0] = __expf(s[nt][0] - mn0);
            s[nt][1] = __expf(s[nt][1] - mn0);
            s[nt][2] = __expf(s[nt][2] - mn1);
            s[nt][3] = __expf(s[nt][3] - mn1);
            rs0 += s[nt][0] + s[nt][1];
            rs1 += s[nt][2] + s[nt][3];
            out[nt][0] *= sc0; out[nt][1] *= sc0;
            out[nt][2] *= sc1; out[nt][3] *= sc1;
        }
        rs0 += __shfl_xor_sync(0xffffffffu, rs0, 1);
        rs0 += __shfl_xor_sync(0xffffffffu, rs0, 2);
        rs1 += __shfl_xor_sync(0xffffffffu, rs1, 1);
        rs1 += __shfl_xor_sync(0xffffffffu, rs1, 2);
        l0 = l0 * sc0 + rs0;
        l1 = l1 * sc1 + rs1;

#pragma unroll
        for (int kg2 = 0; kg2 < 4; kg2++) {
            uint32_t pa[4];
            pa[0] = packh2(s[2 * kg2][0], s[2 * kg2][1]);
            pa[1] = packh2(s[2 * kg2][2], s[2 * kg2][3]);
            pa[2] = packh2(s[2 * kg2 + 1][0], s[2 * kg2 + 1][1]);
            pa[3] = packh2(s[2 * kg2 + 1][2], s[2 * kg2 + 1][3]);
            const uint32_t kbase = (uint32_t)(kg2 * 16 * ASROW) * 2;
#pragma unroll
            for (int ng = 0; ng < 4; ng++) {
                uint32_t rr[4];
                ldsm4t(rr, sV + kbase + (uint32_t)(ng * 32) + voff);
                mma16816(out[2 * ng],     pa, rr);
                mma16816(out[2 * ng + 1], pa, rr + 2);
            }
        }
        __syncthreads();
    }

    const float i0 = 1.0f / l0, i1 = 1.0f / l1;
    const int r0 = qrow0 + g, r1 = qrow0 + g + 8;
    __half* p0 = ctx + ((size_t)(b * Sq + r0) * Hh + h) * DH;
    __half* p1 = ctx + ((size_t)(b * Sq + r1) * Hh + h) * DH;
#pragma unroll
    for (int nt = 0; nt < 8; nt++) {
        const int dh = nt * 8 + tig * 2;
        *(__half2*)(p0 + dh) = __floats2half2_rn(out[nt][0] * i0, out[nt][1] * i0);
        *(__half2*)(p1 + dh) = __floats2half2_rn(out[nt][2] * i1, out[nt][3] * i1);
    }
}

// ---------------- fused add + LayerNorm (fp32 a + fp16 b; optional fp32/fp16 outs) ----
__global__ __launch_bounds__(256)
void addln_kernel(const float* __restrict__ a, const __half* __restrict__ bhp,
                  const float* __restrict__ g, const float* __restrict__ bt,
                  float* __restrict__ o, __half* __restrict__ oh,
                  float* __restrict__ outf) {
    __shared__ float redS[8], redQ[8], outMV[2];
    const int row = blockIdx.x;
    const int t = threadIdx.x;
    const float* ar = a + (size_t)row * Dm;
    const __half* br = bhp + (size_t)row * Dm;

    float v[4];
    float s = 0.f, sq = 0.f;
#pragma unroll
    for (int i = 0; i < 4; i++) {
        int idx = t + i * 256;
        float x = ar[idx] + __half2float(br[idx]);
        v[i] = x;
        s += x;
        sq = fmaf(x, x, sq);
    }
#pragma unroll
    for (int off = 16; off; off >>= 1) {
        s += __shfl_xor_sync(0xFFFFFFFFu, s, off);
        sq += __shfl_xor_sync(0xFFFFFFFFu, sq, off);
    }
    if ((t & 31) == 0) { redS[t >> 5] = s; redQ[t >> 5] = sq; }
    __syncthreads();
    if (t < 32) {
        float s2 = (t < 8) ? redS[t] : 0.f;
        float q2 = (t < 8) ? redQ[t] : 0.f;
#pragma unroll
        for (int off = 4; off; off >>= 1) {
            s2 += __shfl_xor_sync(0xFFFFFFFFu, s2, off);
            q2 += __shfl_xor_sync(0xFFFFFFFFu, q2, off);
        }
        if (t == 0) {
            float mean = s2 * (1.0f / Dm);
            float var = q2 * (1.0f / Dm) - mean * mean;
            outMV[0] = mean;
            outMV[1] = rsqrtf(var + 1e-5f);
        }
    }
    __syncthreads();
    const float mean = outMV[0], rstd = outMV[1];
#pragma unroll
    for (int i = 0; i < 4; i++) {
        int idx = t + i * 256;
        float y = (v[i] - mean) * rstd * g[idx] + bt[idx];
        if (o)    o[(size_t)row * Dm + idx] = y;
        if (oh)   oh[(size_t)row * Dm + idx] = __float2half_rn(y);
        if (outf) outf[(size_t)row * Dm + idx] = y;
    }
}

// ---------------- launch ----------------
extern "C" void kernel_launch(void* const* d_in, const int* in_sizes, int n_in,
                              void* d_out, int out_size) {
    const float* seq  = (const float*)d_in[0];
    const unsigned char* mask = (const unsigned char*)d_in[1];
    const float* Wqkv = (const float*)d_in[2];
    const float* bqkv = (const float*)d_in[3];
    const float* Wo   = (const float*)d_in[4];
    const float* bo   = (const float*)d_in[5];
    const float* g1   = (const float*)d_in[6];
    const float* b1   = (const float*)d_in[7];
    const float* Wi   = (const float*)d_in[8];
    const float* bi   = (const float*)d_in[9];
    const float* Wout = (const float*)d_in[10];
    const float* bout = (const float*)d_in[11];
    const float* g2   = (const float*)d_in[12];
    const float* b2   = (const float*)d_in[13];
    float* out = (float*)d_out;

    __half *seqh, *seql, *Bqkh, *Bqkl, *Bvh, *Woh, *Wih, *Wouth;
    __half *qh, *ql, *kh, *kl, *vh, *ctxh, *xh, *hh, *attnh, *yh;
    float *x;
    cudaGetSymbolAddress((void**)&seqh, g_seqh);   cudaGetSymbolAddress((void**)&seql, g_seql);
    cudaGetSymbolAddress((void**)&Bqkh, g_Bqkh);   cudaGetSymbolAddress((void**)&Bqkl, g_Bqkl);
    cudaGetSymbolAddress((void**)&Bvh, g_Bvh);
    cudaGetSymbolAddress((void**)&Woh, g_Woh);
    cudaGetSymbolAddress((void**)&Wih, g_Wih);
    cudaGetSymbolAddress((void**)&Wouth, g_Wouth);
    cudaGetSymbolAddress((void**)&qh, g_qh);       cudaGetSymbolAddress((void**)&ql, g_ql);
    cudaGetSymbolAddress((void**)&kh, g_kh);       cudaGetSymbolAddress((void**)&kl, g_kl);
    cudaGetSymbolAddress((void**)&vh, g_vh);       cudaGetSymbolAddress((void**)&ctxh, g_ctxh);
    cudaGetSymbolAddress((void**)&xh, g_xh);       cudaGetSymbolAddress((void**)&hh, g_hh);
    cudaGetSymbolAddress((void**)&attnh, g_attnh); cudaGetSymbolAddress((void**)&x, g_x);
    cudaGetSymbolAddress((void**)&yh, g_yh);

    const int SM3 = 3 * 4 * TILE_B;   // 221184 (3-stage)
    const int SM1 = 2 * 2 * TILE_B;   // 73728
    cudaFuncSetAttribute(mma_gemm<3, 3, 1>, cudaFuncAttributeMaxDynamicSharedMemorySize, SM3);
    cudaFuncSetAttribute(mma_gemm<4, 1, 2>, cudaFuncAttributeMaxDynamicSharedMemorySize, SM1);
    cudaFuncSetAttribute(mma_gemm<5, 1, 2>, cudaFuncAttributeMaxDynamicSharedMemorySize, SM1);
    cudaFuncSetAttribute(mma_gemm<2, 1, 2>, cudaFuncAttributeMaxDynamicSharedMemorySize, SM1);
    cudaFuncSetAttribute(attn_mma, cudaFuncAttributeMaxDynamicSharedMemorySize, ATT_SMEM);

    // weight packing
    packW_kernel<<<dim3(4, 32, Hh), dim3(32, 8)>>>(Wqkv, Bqkh, Bqkl, Dm, 192, 0, 128);
    packW_kernel<<<dim3(2, 32, Hh), dim3(32, 8)>>>(Wqkv, Bvh, nullptr, Dm, 192, 128, 64);
    packW_kernel<<<dim3(Dm / 32, Dm / 32, 1), dim3(32, 8)>>>(Wo, Woh, nullptr, Dm, Dm, 0, Dm);
    packW_kernel<<<dim3(Ii / 32, Dm / 32, 1), dim3(32, 8)>>>(Wi, Wih, nullptr, Dm, Ii, 0, Ii);
    packW_kernel<<<dim3(Dm / 32, Ii / 32, 1), dim3(32, 8)>>>(Wout, Wouth, nullptr, Ii, Dm, 0, Dm);

    // seq -> fp16 hi/lo
    split_kernel<<<(ROWS * Dm / 4 + 255) / 256, 256>>>(seq, seqh, seql, ROWS * Dm);

    // QK projection (3-term, 3-stage) -> q(hi/lo)*8, k(hi/lo)
    mma_gemm<3, 3, 1><<<dim3(2048 / 128, ROWS / 128), 256, SM3>>>(
        seqh, seql, Bqkh, Bqkl, bqkv, nullptr, qh, ql, kh, kl, nullptr, nullptr, Dm, 2048);

    // V projection (1-term) -> v fp16
    mma_gemm<4, 1, 2><<<dim3(1024 / 128, ROWS / 128), 256, SM1>>>(
        seqh, nullptr, Bvh, nullptr, bqkv, nullptr,
        nullptr, nullptr, nullptr, nullptr, vh, nullptr, Dm, 1024);

    // tensor-core flash attention -> ctx fp16
    attn_mma<<<dim3(8, Hh, Bz), 256, ATT_SMEM>>>(qh, ql, kh, kl, vh, mask, ctxh);

    // output projection (1-term) -> attn fp16
    mma_gemm<5, 1, 2><<<dim3(Dm / 128, ROWS / 128), 256, SM1>>>(
        ctxh, nullptr, Woh, nullptr, bo, nullptr,
        nullptr, nullptr, nullptr, nullptr, nullptr, attnh, Dm, Dm);

    // x = LN(seq + attn) (fp32 x + fp16 xh)
    addln_kernel<<<ROWS, 256>>>(seq, attnh, g1, b1, x, xh, nullptr);

    // h = gelu(x @ Wi + bi) (1-term) -> fp16
    mma_gemm<2, 1, 2><<<dim3(Ii / 128, ROWS / 128), 256, SM1>>>(
        xh, nullptr, Wih, nullptr, bi, nullptr,
        nullptr, nullptr, nullptr, nullptr, nullptr, hh, Dm, Ii);

    // y = h @ Wout + bout (1-term) -> fp16
    mma_gemm<5, 1, 2><<<dim3(Dm / 128, ROWS / 128), 256, SM1>>>(
        hh, nullptr, Wouth, nullptr, bout, nullptr,
        nullptr, nullptr, nullptr, nullptr, nullptr, yh, Ii, Dm);

    // out = LN(x + y)
    addln_kernel<<<ROWS, 256>>>(x, yh, g2, b2, nullptr, nullptr, out);
}